// round 3
// baseline (speedup 1.0000x reference)
#include <cuda_runtime.h>
#include <math.h>

// Problem constants
#define BB 8
#define SS 4096
#define DM 1024
#define DKK 128
#define DVV 128
#define MMF 256
#define NROWS (BB*SS)           // 32768
#define QK_SCALE 0.29730177875068026f   // 128^-0.25
#define EPSV 1e-6f
#define NCHUNK 16
#define SCH (SS/NCHUNK)         // 256

// Scratch (static device globals -- no allocation allowed)
__device__ float g_q[NROWS*DKK];
__device__ float g_k[NROWS*DKK];
__device__ float g_v[NROWS*DVV];
__device__ float g_phiq[NROWS*MMF];
__device__ float g_pk[NROWS*MMF];
__device__ float g_kv_part[BB*NCHUNK*MMF*DVV];
__device__ float g_ks_part[BB*NCHUNK*MMF];
__device__ float g_kv[BB*MMF*DVV];
__device__ float g_ksum[BB*MMF];
__device__ unsigned int g_gmax_bits;

// Order-preserving float<->uint map for atomicMax on floats (handles negatives)
__device__ __forceinline__ unsigned int fenc(float f){
    unsigned int u = __float_as_uint(f);
    return (u & 0x80000000u) ? ~u : (u | 0x80000000u);
}
__device__ __forceinline__ float fdec(unsigned int u){
    return __uint_as_float((u & 0x80000000u) ? (u ^ 0x80000000u) : ~u);
}

__global__ void k_init(){
    if (threadIdx.x == 0) g_gmax_bits = fenc(-INFINITY);
}

// ---------------------------------------------------------------------------
// K1: fused QKV projection. grid = (NROWS/128, 3). C tile 128x128, BK=8,
// 256 threads, 8x8 microtile.  out = (x @ W + b) * scale
// ---------------------------------------------------------------------------
__global__ __launch_bounds__(256,1) void k_qkv(
    const float* __restrict__ x,
    const float* __restrict__ Wq, const float* __restrict__ bq,
    const float* __restrict__ Wk, const float* __restrict__ bk,
    const float* __restrict__ Wv, const float* __restrict__ bv)
{
    __shared__ float As[8][132];   // [k][m] (transposed A)
    __shared__ float Bs[8][132];   // [k][n]
    const int t = threadIdx.x;
    const int which = blockIdx.y;
    const float* W   = (which==0)?Wq:((which==1)?Wk:Wv);
    const float* bia = (which==0)?bq:((which==1)?bk:bv);
    float* outp      = (which==0)?g_q:((which==1)?g_k:g_v);
    const float scale = (which==2)?1.0f:QK_SCALE;
    const int row0 = blockIdx.x*128;
    const int ty = t>>4, tx = t&15;
    const int ar = t>>1,  ac = (t&1)*4;
    const int br = t>>5,  bc = (t&31)*4;

    float acc[8][8];
    #pragma unroll
    for (int i=0;i<8;i++)
        #pragma unroll
        for (int j=0;j<8;j++) acc[i][j]=0.f;

    for (int k0=0;k0<DM;k0+=8){
        float4 av  = *(const float4*)(x + (size_t)(row0+ar)*DM + k0 + ac);
        float4 bv4 = *(const float4*)(W + (size_t)(k0+br)*DKK + bc);
        __syncthreads();
        As[ac+0][ar]=av.x; As[ac+1][ar]=av.y; As[ac+2][ar]=av.z; As[ac+3][ar]=av.w;
        *(float4*)&Bs[br][bc] = bv4;
        __syncthreads();
        #pragma unroll
        for (int kk=0;kk<8;kk++){
            float a[8], b[8];
            *(float4*)&a[0] = *(const float4*)&As[kk][ty*8];
            *(float4*)&a[4] = *(const float4*)&As[kk][ty*8+4];
            *(float4*)&b[0] = *(const float4*)&Bs[kk][tx*8];
            *(float4*)&b[4] = *(const float4*)&Bs[kk][tx*8+4];
            #pragma unroll
            for (int i=0;i<8;i++)
                #pragma unroll
                for (int j=0;j<8;j++) acc[i][j] += a[i]*b[j];
        }
    }
    #pragma unroll
    for (int i=0;i<8;i++){
        const int row = row0 + ty*8 + i;
        #pragma unroll
        for (int j4=0;j4<8;j4+=4){
            float4 o;
            o.x = (acc[i][j4+0] + bia[tx*8+j4+0])*scale;
            o.y = (acc[i][j4+1] + bia[tx*8+j4+1])*scale;
            o.z = (acc[i][j4+2] + bia[tx*8+j4+2])*scale;
            o.w = (acc[i][j4+3] + bia[tx*8+j4+3])*scale;
            *(float4*)(outp + (size_t)row*DKK + tx*8 + j4) = o;
        }
    }
}

// ---------------------------------------------------------------------------
// K2: feature projections. grid = (NROWS/32, 2): y==0 -> q path (emit phi_q
// with per-row max), y==1 -> k path (emit raw pk + global max via atomicMax).
// omega (256x128) held in smem; each thread computes a 4m x 8row tile.
// ---------------------------------------------------------------------------
#define K2_OST 129
#define K2_RST 132
#define K2_PST 257
#define K2_SMEM_FLOATS (256*K2_OST + 32*K2_RST + 32*K2_PST + 32 + 32 + 8)

__global__ __launch_bounds__(256,1) void k_feat(const float* __restrict__ omega)
{
    extern __shared__ float sm2[];
    float* om_s = sm2;
    float* rw_s = om_s + 256*K2_OST;
    float* pq_s = rw_s + 32*K2_RST;
    float* sq_s = pq_s + 32*K2_PST;
    float* rx_s = sq_s + 32;
    float* rd_s = rx_s + 32;
    const int t = threadIdx.x;
    const int isK = blockIdx.y;
    const float* src = isK ? g_k : g_q;
    const int row0 = blockIdx.x*32;

    #pragma unroll
    for (int i=0;i<32;i++){
        int idx = t + i*256;
        int m = idx>>5, j = (idx&31)*4;
        float4 v = *(const float4*)(omega + (size_t)m*DKK + j);
        float* d = &om_s[m*K2_OST + j];
        d[0]=v.x; d[1]=v.y; d[2]=v.z; d[3]=v.w;
    }
    #pragma unroll
    for (int i=0;i<4;i++){
        int idx = t + i*256;
        int r = idx>>5, j = (idx&31)*4;
        float4 v = *(const float4*)(src + (size_t)(row0+r)*DKK + j);
        *(float4*)&rw_s[r*K2_RST + j] = v;
    }
    __syncthreads();
    {   // 0.5*||row||^2
        int r = t>>3, c = t&7;
        float s=0.f;
        #pragma unroll
        for (int j=0;j<16;j++){ float v = rw_s[r*K2_RST + c*16 + j]; s += v*v; }
        s += __shfl_down_sync(0xffffffffu, s, 4, 8);
        s += __shfl_down_sync(0xffffffffu, s, 2, 8);
        s += __shfl_down_sync(0xffffffffu, s, 1, 8);
        if (c==0) sq_s[r] = 0.5f*s;
    }
    __syncthreads();

    const int mb = t&63;            // m = mb + 64*mi
    const int r0 = (t>>6)*8;        // 8 rows per thread
    float acc[4][8];
    #pragma unroll
    for (int mi=0;mi<4;mi++)
        #pragma unroll
        for (int ri=0;ri<8;ri++) acc[mi][ri]=0.f;

    for (int j4=0;j4<DKK;j4+=4){
        float rv[8][4];
        #pragma unroll
        for (int ri=0;ri<8;ri++){
            float4 v = *(const float4*)&rw_s[(r0+ri)*K2_RST + j4];
            rv[ri][0]=v.x; rv[ri][1]=v.y; rv[ri][2]=v.z; rv[ri][3]=v.w;
        }
        float om[4][4];
        #pragma unroll
        for (int mi=0;mi<4;mi++)
            #pragma unroll
            for (int u=0;u<4;u++) om[mi][u] = om_s[(mb + mi*64)*K2_OST + j4 + u];
        #pragma unroll
        for (int u=0;u<4;u++)
            #pragma unroll
            for (int mi=0;mi<4;mi++)
                #pragma unroll
                for (int ri=0;ri<8;ri++) acc[mi][ri] += om[mi][u]*rv[ri][u];
    }
    #pragma unroll
    for (int mi=0;mi<4;mi++)
        #pragma unroll
        for (int ri=0;ri<8;ri++)
            pq_s[(r0+ri)*K2_PST + mb + mi*64] = acc[mi][ri] - sq_s[r0+ri];
    __syncthreads();

    if (!isK){
        int r = t>>3, c = t&7;
        float mx = -INFINITY;
        #pragma unroll
        for (int i=0;i<32;i++) mx = fmaxf(mx, pq_s[r*K2_PST + c + 8*i]);
        mx = fmaxf(mx, __shfl_down_sync(0xffffffffu, mx, 4, 8));
        mx = fmaxf(mx, __shfl_down_sync(0xffffffffu, mx, 2, 8));
        mx = fmaxf(mx, __shfl_down_sync(0xffffffffu, mx, 1, 8));
        if (c==0) rx_s[r] = mx;
        __syncthreads();
        float* dst = g_phiq + (size_t)row0*MMF;
        for (int r2=0;r2<32;r2++)
            dst[r2*MMF + t] = __expf(pq_s[r2*K2_PST + t] - rx_s[r2]) * 0.0625f;
    } else {
        float mx = -INFINITY;
        float* dst = g_pk + (size_t)row0*MMF;
        for (int r2=0;r2<32;r2++){
            float v = pq_s[r2*K2_PST + t];
            dst[r2*MMF + t] = v;
            mx = fmaxf(mx, v);
        }
        #pragma unroll
        for (int o=16;o>0;o>>=1) mx = fmaxf(mx, __shfl_down_sync(0xffffffffu, mx, o));
        if ((t&31)==0) rd_s[t>>5] = mx;
        __syncthreads();
        if (t==0){
            float m2 = rd_s[0];
            #pragma unroll
            for (int i=1;i<8;i++) m2 = fmaxf(m2, rd_s[i]);
            atomicMax(&g_gmax_bits, fenc(m2));
        }
    }
}

// ---------------------------------------------------------------------------
// K3: kv[b] partials = phi_k^T @ v over an S-chunk (exp fused at load).
// grid = (B*NCHUNK, 2 m-tiles). Deterministic: per-chunk partial buffers.
// ---------------------------------------------------------------------------
__global__ __launch_bounds__(256,1) void k_kv()
{
    __shared__ float As[8][132];   // [s][m] = phi_k
    __shared__ float Bs[8][132];   // [s][d] = v
    __shared__ float ks_s[128];
    const int t = threadIdx.x;
    const int b = blockIdx.x >> 4;
    const int chunk = blockIdx.x & 15;
    const int mtile = blockIdx.y;
    const float gmax = fdec(g_gmax_bits);
    const int ty = t>>4, tx = t&15;
    const int sr = t>>5, c4 = (t&31)*4;
    const size_t srow_base = (size_t)(b*SS + chunk*SCH + sr);

    float acc[8][8];
    #pragma unroll
    for (int i=0;i<8;i++)
        #pragma unroll
        for (int j=0;j<8;j++) acc[i][j]=0.f;
    float ksl[4] = {0.f,0.f,0.f,0.f};

    for (int s0=0;s0<SCH;s0+=8){
        const size_t srow = srow_base + s0;
        float4 pv = *(const float4*)(g_pk + srow*MMF + mtile*128 + c4);
        float4 vv = *(const float4*)(g_v  + srow*DVV + c4);
        float4 ev;
        ev.x = __expf(pv.x - gmax)*0.0625f;
        ev.y = __expf(pv.y - gmax)*0.0625f;
        ev.z = __expf(pv.z - gmax)*0.0625f;
        ev.w = __expf(pv.w - gmax)*0.0625f;
        ksl[0]+=ev.x; ksl[1]+=ev.y; ksl[2]+=ev.z; ksl[3]+=ev.w;
        __syncthreads();
        *(float4*)&As[sr][c4] = ev;
        *(float4*)&Bs[sr][c4] = vv;
        __syncthreads();
        #pragma unroll
        for (int kk=0;kk<8;kk++){
            float a[8], bb2[8];
            *(float4*)&a[0]   = *(const float4*)&As[kk][ty*8];
            *(float4*)&a[4]   = *(const float4*)&As[kk][ty*8+4];
            *(float4*)&bb2[0] = *(const float4*)&Bs[kk][tx*8];
            *(float4*)&bb2[4] = *(const float4*)&Bs[kk][tx*8+4];
            #pragma unroll
            for (int i=0;i<8;i++)
                #pragma unroll
                for (int j=0;j<8;j++) acc[i][j] += a[i]*bb2[j];
        }
    }
    float* kvp = g_kv_part + (size_t)(b*NCHUNK + chunk)*MMF*DVV + (size_t)mtile*128*DVV;
    #pragma unroll
    for (int i=0;i<8;i++){
        const int m = ty*8+i;
        #pragma unroll
        for (int j4=0;j4<8;j4+=4){
            float4 o; o.x=acc[i][j4]; o.y=acc[i][j4+1]; o.z=acc[i][j4+2]; o.w=acc[i][j4+3];
            *(float4*)(kvp + (size_t)m*DVV + tx*8 + j4) = o;
        }
    }
    if (t<128) ks_s[t]=0.f;
    __syncthreads();
    atomicAdd(&ks_s[c4+0], ksl[0]);
    atomicAdd(&ks_s[c4+1], ksl[1]);
    atomicAdd(&ks_s[c4+2], ksl[2]);
    atomicAdd(&ks_s[c4+3], ksl[3]);
    __syncthreads();
    if (t<128)
        g_ks_part[(size_t)(b*NCHUNK+chunk)*MMF + mtile*128 + t] = ks_s[t];
}

// K3b: reduce chunk partials (deterministic)
__global__ void k_kvred(){
    const int idx = blockIdx.x*256 + threadIdx.x;
    const int KVTOT = BB*MMF*DVV;   // 262144
    if (idx < KVTOT){
        const int b = idx >> 15;
        const int rem = idx & 32767;
        float s=0.f;
        #pragma unroll
        for (int c=0;c<NCHUNK;c++) s += g_kv_part[(size_t)(b*NCHUNK+c)*MMF*DVV + rem];
        g_kv[idx]=s;
    } else {
        const int j = idx - KVTOT;
        if (j < BB*MMF){
            const int b = j >> 8; const int m = j & 255;
            float s=0.f;
            #pragma unroll
            for (int c=0;c<NCHUNK;c++) s += g_ks_part[(size_t)(b*NCHUNK+c)*MMF + m];
            g_ksum[j]=s;
        }
    }
}

// ---------------------------------------------------------------------------
// K4: out = (phi_q @ kv[b]) / (phi_q . ksum[b] + eps). kv[b] resident in smem.
// grid = (S/32, B), 32 rows per block.
// ---------------------------------------------------------------------------
#define K4_SMEM_FLOATS (MMF*DVV + 256 + 32*257 + 32)

__global__ __launch_bounds__(256,1) void k_out(float* __restrict__ outp)
{
    extern __shared__ float sm4[];
    float* kv_s = sm4;
    float* ks_s = kv_s + MMF*DVV;
    float* ph_s = ks_s + 256;
    float* id_s = ph_s + 32*257;
    const int t = threadIdx.x;
    const int b = blockIdx.y;
    const int row0 = blockIdx.x*32;

    #pragma unroll
    for (int i=0;i<32;i++){
        const int idx = (t + i*256)*4;
        *(float4*)&kv_s[idx] = *(const float4*)(g_kv + (size_t)b*MMF*DVV + idx);
    }
    ks_s[t] = g_ksum[b*MMF + t];
    #pragma unroll
    for (int i=0;i<8;i++){
        const int idx = t + i*256;
        const int r = idx>>6, c = (idx&63)*4;
        float4 v = *(const float4*)(g_phiq + (size_t)(b*SS + row0 + r)*MMF + c);
        float* d = &ph_s[r*257 + c];
        d[0]=v.x; d[1]=v.y; d[2]=v.z; d[3]=v.w;
    }
    __syncthreads();
    {
        int r = t>>3, c = t&7;
        float s=0.f;
        #pragma unroll
        for (int i=0;i<32;i++){ const int m = c + 8*i; s += ph_s[r*257 + m]*ks_s[m]; }
        s += __shfl_down_sync(0xffffffffu, s, 4, 8);
        s += __shfl_down_sync(0xffffffffu, s, 2, 8);
        s += __shfl_down_sync(0xffffffffu, s, 1, 8);
        if (c==0) id_s[r] = 1.0f/(s + EPSV);
    }
    __syncthreads();
    const int tx = t&31, ty = t>>5;
    float acc[4][4];
    #pragma unroll
    for (int ri=0;ri<4;ri++)
        #pragma unroll
        for (int u=0;u<4;u++) acc[ri][u]=0.f;
    for (int m=0;m<MMF;m++){
        float4 kvv = *(const float4*)&kv_s[m*DVV + tx*4];
        #pragma unroll
        for (int ri=0;ri<4;ri++){
            const float p = ph_s[(ty + ri*8)*257 + m];
            acc[ri][0] += p*kvv.x;
            acc[ri][1] += p*kvv.y;
            acc[ri][2] += p*kvv.z;
            acc[ri][3] += p*kvv.w;
        }
    }
    #pragma unroll
    for (int ri=0;ri<4;ri++){
        const int r = ty + ri*8;
        const float idn = id_s[r];
        float4 o; o.x=acc[ri][0]*idn; o.y=acc[ri][1]*idn; o.z=acc[ri][2]*idn; o.w=acc[ri][3]*idn;
        *(float4*)(outp + (size_t)(b*SS + row0 + r)*DVV + tx*4) = o;
    }
}

// ---------------------------------------------------------------------------
extern "C" void kernel_launch(void* const* d_in, const int* in_sizes, int n_in,
                              void* d_out, int out_size)
{
    (void)in_sizes; (void)n_in; (void)out_size;
    const float* x     = (const float*)d_in[0];
    const float* Wq    = (const float*)d_in[1];
    const float* bq    = (const float*)d_in[2];
    const float* Wk    = (const float*)d_in[3];
    const float* bk    = (const float*)d_in[4];
    const float* Wv    = (const float*)d_in[5];
    const float* bv    = (const float*)d_in[6];
    const float* omega = (const float*)d_in[7];
    float* outp = (float*)d_out;

    const int k2_smem = K2_SMEM_FLOATS * (int)sizeof(float);
    const int k4_smem = K4_SMEM_FLOATS * (int)sizeof(float);
    cudaFuncSetAttribute(k_feat, cudaFuncAttributeMaxDynamicSharedMemorySize, k2_smem);
    cudaFuncSetAttribute(k_out,  cudaFuncAttributeMaxDynamicSharedMemorySize, k4_smem);

    k_init<<<1, 32>>>();
    k_qkv<<<dim3(NROWS/128, 3), 256>>>(x, Wq, bq, Wk, bk, Wv, bv);
    k_feat<<<dim3(NROWS/32, 2), 256, k2_smem>>>(omega);
    k_kv<<<dim3(BB*NCHUNK, 2), 256>>>();
    k_kvred<<<(BB*MMF*DVV + BB*MMF + 255)/256, 256>>>();
    k_out<<<dim3(SS/32, BB), 256, k4_smem>>>(outp);
}

// round 6
// speedup vs baseline: 1.2118x; 1.2118x over previous
#include <cuda_runtime.h>
#include <math.h>

// Problem constants
#define BB 8
#define SS 4096
#define DM 1024
#define DKK 128
#define DVV 128
#define MMF 256
#define NROWS (BB*SS)           // 32768
#define QK_SCALE 0.29730177875068026f   // 128^-0.25
#define EPSV 1e-6f
#define NCHUNK 16
#define SCH (SS/NCHUNK)         // 256

typedef unsigned long long ull;

// f32x2 SIMD helpers (sm_100+ packed fp32; FFMA2 in SASS)
__device__ __forceinline__ ull f2_dup(float a){
    ull r; asm("mov.b64 %0, {%1, %1};" : "=l"(r) : "f"(a)); return r;
}
__device__ __forceinline__ ull f2_pack(float lo, float hi){
    ull r; asm("mov.b64 %0, {%1, %2};" : "=l"(r) : "f"(lo), "f"(hi)); return r;
}
__device__ __forceinline__ void f2_unpack(ull v, float& lo, float& hi){
    asm("mov.b64 {%0, %1}, %2;" : "=f"(lo), "=f"(hi) : "l"(v));
}
__device__ __forceinline__ void f2_fma(ull& d, ull a, ull b){
    asm("fma.rn.f32x2 %0, %1, %2, %3;" : "=l"(d) : "l"(a), "l"(b), "l"(d));
}

// Scratch (static device globals -- no allocation allowed)
__device__ float g_q[NROWS*DKK];
__device__ float g_k[NROWS*DKK];
__device__ float g_v[NROWS*DVV];
__device__ float g_phiq[NROWS*MMF];
__device__ float g_pk[NROWS*MMF];
__device__ float g_kv_part[BB*NCHUNK*MMF*DVV];
__device__ float g_ks_part[BB*NCHUNK*MMF];
__device__ float g_kv[BB*MMF*DVV];
__device__ float g_ksum[BB*MMF];
__device__ unsigned int g_gmax_bits;

// Order-preserving float<->uint map for atomicMax on floats (handles negatives)
__device__ __forceinline__ unsigned int fenc(float f){
    unsigned int u = __float_as_uint(f);
    return (u & 0x80000000u) ? ~u : (u | 0x80000000u);
}
__device__ __forceinline__ float fdec(unsigned int u){
    return __uint_as_float((u & 0x80000000u) ? (u ^ 0x80000000u) : ~u);
}

__global__ void k_init(){
    if (threadIdx.x == 0) g_gmax_bits = fenc(-INFINITY);
}

// ---------------------------------------------------------------------------
// K1: fused QKV projection. grid = (NROWS/128, 3). C tile 128x128, BK=8,
// 256 threads, FFMA2 microtile: rows {ty*4..+3, 64+ty*4..+3}, cols
// {tx*4..+3, 64+tx*4..+3}.  out = (x @ W + b) * scale
// A-side smem loads are 16-lane broadcasts (free); B-side float4 loads are
// conflict-free (stride-4-float across 8-lane phases covers banks 0..31).
// ---------------------------------------------------------------------------
__global__ __launch_bounds__(256,2) void k_qkv(
    const float* __restrict__ x,
    const float* __restrict__ Wq, const float* __restrict__ bq,
    const float* __restrict__ Wk, const float* __restrict__ bk,
    const float* __restrict__ Wv, const float* __restrict__ bv)
{
    __shared__ float As[8][132];   // [k][m] (transposed A)
    __shared__ float Bs[8][132];   // [k][n]
    const int t = threadIdx.x;
    const int which = blockIdx.y;
    const float* W   = (which==0)?Wq:((which==1)?Wk:Wv);
    const float* bia = (which==0)?bq:((which==1)?bk:bv);
    float* outp      = (which==0)?g_q:((which==1)?g_k:g_v);
    const float scale = (which==2)?1.0f:QK_SCALE;
    const int row0 = blockIdx.x*128;
    const int ty = t>>4, tx = t&15;
    const int ar = t>>1,  ac = (t&1)*4;
    const int br = t>>5,  bc = (t&31)*4;

    ull acc2[8][4];
    #pragma unroll
    for (int i=0;i<8;i++)
        #pragma unroll
        for (int j=0;j<4;j++) acc2[i][j]=0ull;

    for (int k0=0;k0<DM;k0+=8){
        float4 av  = *(const float4*)(x + (size_t)(row0+ar)*DM + k0 + ac);
        float4 bv4 = *(const float4*)(W + (size_t)(k0+br)*DKK + bc);
        __syncthreads();
        As[ac+0][ar]=av.x; As[ac+1][ar]=av.y; As[ac+2][ar]=av.z; As[ac+3][ar]=av.w;
        *(float4*)&Bs[br][bc] = bv4;
        __syncthreads();
        #pragma unroll
        for (int kk=0;kk<8;kk++){
            float4 a0 = *(const float4*)&As[kk][ty*4];
            float4 a1 = *(const float4*)&As[kk][64+ty*4];
            float4 b0 = *(const float4*)&Bs[kk][tx*4];
            float4 b1 = *(const float4*)&Bs[kk][64+tx*4];
            ull bb0 = f2_pack(b0.x,b0.y), bb1 = f2_pack(b0.z,b0.w);
            ull bb2 = f2_pack(b1.x,b1.y), bb3 = f2_pack(b1.z,b1.w);
            ull aa[8];
            aa[0]=f2_dup(a0.x); aa[1]=f2_dup(a0.y); aa[2]=f2_dup(a0.z); aa[3]=f2_dup(a0.w);
            aa[4]=f2_dup(a1.x); aa[5]=f2_dup(a1.y); aa[6]=f2_dup(a1.z); aa[7]=f2_dup(a1.w);
            #pragma unroll
            for (int i=0;i<8;i++){
                f2_fma(acc2[i][0], aa[i], bb0);
                f2_fma(acc2[i][1], aa[i], bb1);
                f2_fma(acc2[i][2], aa[i], bb2);
                f2_fma(acc2[i][3], aa[i], bb3);
            }
        }
    }
    #pragma unroll
    for (int i=0;i<8;i++){
        const int row = row0 + ((i<4)? (ty*4+i) : (64+ty*4+(i-4)));
        float p0,p1,p2,p3;
        {
            const int c = tx*4;
            f2_unpack(acc2[i][0], p0, p1);
            f2_unpack(acc2[i][1], p2, p3);
            float4 o;
            o.x=(p0+bia[c+0])*scale; o.y=(p1+bia[c+1])*scale;
            o.z=(p2+bia[c+2])*scale; o.w=(p3+bia[c+3])*scale;
            *(float4*)(outp + (size_t)row*DKK + c) = o;
        }
        {
            const int c = 64+tx*4;
            f2_unpack(acc2[i][2], p0, p1);
            f2_unpack(acc2[i][3], p2, p3);
            float4 o;
            o.x=(p0+bia[c+0])*scale; o.y=(p1+bia[c+1])*scale;
            o.z=(p2+bia[c+2])*scale; o.w=(p3+bia[c+3])*scale;
            *(float4*)(outp + (size_t)row*DKK + c) = o;
        }
    }
}

// ---------------------------------------------------------------------------
// K2: feature projections. grid = (NROWS/32, 2): y==0 -> q path (emit phi_q
// with per-row max), y==1 -> k path (emit raw pk + global max via atomicMax).
// omega (256x128) held in smem; FFMA2 dot-product (packed along reduction u).
// ---------------------------------------------------------------------------
#define K2_OST 132
#define K2_RST 132
#define K2_PST 257
#define K2_SMEM_FLOATS (256*K2_OST + 32*K2_RST + 32*K2_PST + 32 + 32 + 8)

__global__ __launch_bounds__(256,1) void k_feat(const float* __restrict__ omega)
{
    extern __shared__ float sm2[];
    float* om_s = sm2;
    float* rw_s = om_s + 256*K2_OST;
    float* pq_s = rw_s + 32*K2_RST;
    float* sq_s = pq_s + 32*K2_PST;
    float* rx_s = sq_s + 32;
    float* rd_s = rx_s + 32;
    const int t = threadIdx.x;
    const int isK = blockIdx.y;
    const float* src = isK ? g_k : g_q;
    const int row0 = blockIdx.x*32;

    #pragma unroll
    for (int i=0;i<32;i++){
        int idx = t + i*256;
        int m = idx>>5, j = (idx&31)*4;
        float4 v = *(const float4*)(omega + (size_t)m*DKK + j);
        *(float4*)&om_s[m*K2_OST + j] = v;
    }
    #pragma unroll
    for (int i=0;i<4;i++){
        int idx = t + i*256;
        int r = idx>>5, j = (idx&31)*4;
        float4 v = *(const float4*)(src + (size_t)(row0+r)*DKK + j);
        *(float4*)&rw_s[r*K2_RST + j] = v;
    }
    __syncthreads();
    {   // 0.5*||row||^2
        int r = t>>3, c = t&7;
        float s=0.f;
        #pragma unroll
        for (int j=0;j<16;j++){ float v = rw_s[r*K2_RST + c*16 + j]; s += v*v; }
        s += __shfl_down_sync(0xffffffffu, s, 4, 8);
        s += __shfl_down_sync(0xffffffffu, s, 2, 8);
        s += __shfl_down_sync(0xffffffffu, s, 1, 8);
        if (c==0) sq_s[r] = 0.5f*s;
    }
    __syncthreads();

    const int mb = t&63;            // m = mb + 64*mi
    const int r0 = (t>>6)*8;        // 8 rows per thread
    ull acc2[4][8];
    #pragma unroll
    for (int mi=0;mi<4;mi++)
        #pragma unroll
        for (int ri=0;ri<8;ri++) acc2[mi][ri]=0ull;

    for (int j4=0;j4<DKK;j4+=4){
        ull rp0[8], rp1[8];
        #pragma unroll
        for (int ri=0;ri<8;ri++){
            float4 v = *(const float4*)&rw_s[(r0+ri)*K2_RST + j4];
            rp0[ri]=f2_pack(v.x,v.y); rp1[ri]=f2_pack(v.z,v.w);
        }
        #pragma unroll
        for (int mi=0;mi<4;mi++){
            float4 w = *(const float4*)&om_s[(mb + mi*64)*K2_OST + j4];
            ull o0=f2_pack(w.x,w.y), o1=f2_pack(w.z,w.w);
            #pragma unroll
            for (int ri=0;ri<8;ri++){
                f2_fma(acc2[mi][ri], o0, rp0[ri]);
                f2_fma(acc2[mi][ri], o1, rp1[ri]);
            }
        }
    }
    #pragma unroll
    for (int mi=0;mi<4;mi++)
        #pragma unroll
        for (int ri=0;ri<8;ri++){
            float lo,hi; f2_unpack(acc2[mi][ri], lo, hi);
            pq_s[(r0+ri)*K2_PST + mb + mi*64] = (lo+hi) - sq_s[r0+ri];
        }
    __syncthreads();

    if (!isK){
        int r = t>>3, c = t&7;
        float mx = -INFINITY;
        #pragma unroll
        for (int i=0;i<32;i++) mx = fmaxf(mx, pq_s[r*K2_PST + c + 8*i]);
        mx = fmaxf(mx, __shfl_down_sync(0xffffffffu, mx, 4, 8));
        mx = fmaxf(mx, __shfl_down_sync(0xffffffffu, mx, 2, 8));
        mx = fmaxf(mx, __shfl_down_sync(0xffffffffu, mx, 1, 8));
        if (c==0) rx_s[r] = mx;
        __syncthreads();
        float* dst = g_phiq + (size_t)row0*MMF;
        for (int r2=0;r2<32;r2++)
            dst[r2*MMF + t] = __expf(pq_s[r2*K2_PST + t] - rx_s[r2]) * 0.0625f;
    } else {
        float mx = -INFINITY;
        float* dst = g_pk + (size_t)row0*MMF;
        for (int r2=0;r2<32;r2++){
            float v = pq_s[r2*K2_PST + t];
            dst[r2*MMF + t] = v;
            mx = fmaxf(mx, v);
        }
        #pragma unroll
        for (int o=16;o>0;o>>=1) mx = fmaxf(mx, __shfl_down_sync(0xffffffffu, mx, o));
        if ((t&31)==0) rd_s[t>>5] = mx;
        __syncthreads();
        if (t==0){
            float m2 = rd_s[0];
            #pragma unroll
            for (int i=1;i<8;i++) m2 = fmaxf(m2, rd_s[i]);
            atomicMax(&g_gmax_bits, fenc(m2));
        }
    }
}

// ---------------------------------------------------------------------------
// K3: kv[b] partials = phi_k^T @ v over an S-chunk (exp fused at load).
// grid = (B*NCHUNK, 2 m-tiles). Deterministic: per-chunk partial buffers.
// FFMA2 microtile as in K1.
// ---------------------------------------------------------------------------
__global__ __launch_bounds__(256,2) void k_kv()
{
    __shared__ float As[8][132];   // [s][m] = phi_k
    __shared__ float Bs[8][132];   // [s][d] = v
    __shared__ float ks_s[128];
    const int t = threadIdx.x;
    const int b = blockIdx.x >> 4;
    const int chunk = blockIdx.x & 15;
    const int mtile = blockIdx.y;
    const float gmax = fdec(g_gmax_bits);
    const int ty = t>>4, tx = t&15;
    const int sr = t>>5, c4 = (t&31)*4;
    const size_t srow_base = (size_t)(b*SS + chunk*SCH + sr);

    ull acc2[8][4];
    #pragma unroll
    for (int i=0;i<8;i++)
        #pragma unroll
        for (int j=0;j<4;j++) acc2[i][j]=0ull;
    float ksl[4] = {0.f,0.f,0.f,0.f};

    for (int s0=0;s0<SCH;s0+=8){
        const size_t srow = srow_base + s0;
        float4 pv = *(const float4*)(g_pk + srow*MMF + mtile*128 + c4);
        float4 vv = *(const float4*)(g_v  + srow*DVV + c4);
        float4 ev;
        ev.x = __expf(pv.x - gmax)*0.0625f;
        ev.y = __expf(pv.y - gmax)*0.0625f;
        ev.z = __expf(pv.z - gmax)*0.0625f;
        ev.w = __expf(pv.w - gmax)*0.0625f;
        ksl[0]+=ev.x; ksl[1]+=ev.y; ksl[2]+=ev.z; ksl[3]+=ev.w;
        __syncthreads();
        *(float4*)&As[sr][c4] = ev;
        *(float4*)&Bs[sr][c4] = vv;
        __syncthreads();
        #pragma unroll
        for (int kk=0;kk<8;kk++){
            float4 a0 = *(const float4*)&As[kk][ty*4];
            float4 a1 = *(const float4*)&As[kk][64+ty*4];
            float4 b0 = *(const float4*)&Bs[kk][tx*4];
            float4 b1 = *(const float4*)&Bs[kk][64+tx*4];
            ull bb0 = f2_pack(b0.x,b0.y), bb1 = f2_pack(b0.z,b0.w);
            ull bb2 = f2_pack(b1.x,b1.y), bb3 = f2_pack(b1.z,b1.w);
            ull aa[8];
            aa[0]=f2_dup(a0.x); aa[1]=f2_dup(a0.y); aa[2]=f2_dup(a0.z); aa[3]=f2_dup(a0.w);
            aa[4]=f2_dup(a1.x); aa[5]=f2_dup(a1.y); aa[6]=f2_dup(a1.z); aa[7]=f2_dup(a1.w);
            #pragma unroll
            for (int i=0;i<8;i++){
                f2_fma(acc2[i][0], aa[i], bb0);
                f2_fma(acc2[i][1], aa[i], bb1);
                f2_fma(acc2[i][2], aa[i], bb2);
                f2_fma(acc2[i][3], aa[i], bb3);
            }
        }
    }
    float* kvp = g_kv_part + (size_t)(b*NCHUNK + chunk)*MMF*DVV + (size_t)mtile*128*DVV;
    #pragma unroll
    for (int i=0;i<8;i++){
        const int m = (i<4)? (ty*4+i) : (64+ty*4+(i-4));
        float p0,p1,p2,p3;
        {
            f2_unpack(acc2[i][0], p0, p1);
            f2_unpack(acc2[i][1], p2, p3);
            float4 o; o.x=p0; o.y=p1; o.z=p2; o.w=p3;
            *(float4*)(kvp + (size_t)m*DVV + tx*4) = o;
        }
        {
            f2_unpack(acc2[i][2], p0, p1);
            f2_unpack(acc2[i][3], p2, p3);
            float4 o; o.x=p0; o.y=p1; o.z=p2; o.w=p3;
            *(float4*)(kvp + (size_t)m*DVV + 64 + tx*4) = o;
        }
    }
    if (t<128) ks_s[t]=0.f;
    __syncthreads();
    atomicAdd(&ks_s[c4+0], ksl[0]);
    atomicAdd(&ks_s[c4+1], ksl[1]);
    atomicAdd(&ks_s[c4+2], ksl[2]);
    atomicAdd(&ks_s[c4+3], ksl[3]);
    __syncthreads();
    if (t<128)
        g_ks_part[(size_t)(b*NCHUNK+chunk)*MMF + mtile*128 + t] = ks_s[t];
}

// K3b: reduce chunk partials (deterministic)
__global__ void k_kvred(){
    const int idx = blockIdx.x*256 + threadIdx.x;
    const int KVTOT = BB*MMF*DVV;   // 262144
    if (idx < KVTOT){
        const int b = idx >> 15;
        const int rem = idx & 32767;
        float s=0.f;
        #pragma unroll
        for (int c=0;c<NCHUNK;c++) s += g_kv_part[(size_t)(b*NCHUNK+c)*MMF*DVV + rem];
        g_kv[idx]=s;
    } else {
        const int j = idx - KVTOT;
        if (j < BB*MMF){
            const int b = j >> 8; const int m = j & 255;
            float s=0.f;
            #pragma unroll
            for (int c=0;c<NCHUNK;c++) s += g_ks_part[(size_t)(b*NCHUNK+c)*MMF + m];
            g_ksum[j]=s;
        }
    }
}

// ---------------------------------------------------------------------------
// K4: out = (phi_q @ kv[b]) / (phi_q . ksum[b] + eps). kv[b] resident in smem.
// grid = (S/32, B), 32 rows per block. FFMA2 along DV.
// ---------------------------------------------------------------------------
#define K4_SMEM_FLOATS (MMF*DVV + 256 + 32*257 + 32)

__global__ __launch_bounds__(256,1) void k_out(float* __restrict__ outp)
{
    extern __shared__ float sm4[];
    float* kv_s = sm4;
    float* ks_s = kv_s + MMF*DVV;
    float* ph_s = ks_s + 256;
    float* id_s = ph_s + 32*257;
    const int t = threadIdx.x;
    const int b = blockIdx.y;
    const int row0 = blockIdx.x*32;

    #pragma unroll
    for (int i=0;i<32;i++){
        const int idx = (t + i*256)*4;
        *(float4*)&kv_s[idx] = *(const float4*)(g_kv + (size_t)b*MMF*DVV + idx);
    }
    ks_s[t] = g_ksum[b*MMF + t];
    #pragma unroll
    for (int i=0;i<8;i++){
        const int idx = t + i*256;
        const int r = idx>>6, c = (idx&63)*4;
        float4 v = *(const float4*)(g_phiq + (size_t)(b*SS + row0 + r)*MMF + c);
        float* d = &ph_s[r*257 + c];
        d[0]=v.x; d[1]=v.y; d[2]=v.z; d[3]=v.w;
    }
    __syncthreads();
    {
        int r = t>>3, c = t&7;
        float s=0.f;
        #pragma unroll
        for (int i=0;i<32;i++){ const int m = c + 8*i; s += ph_s[r*257 + m]*ks_s[m]; }
        s += __shfl_down_sync(0xffffffffu, s, 4, 8);
        s += __shfl_down_sync(0xffffffffu, s, 2, 8);
        s += __shfl_down_sync(0xffffffffu, s, 1, 8);
        if (c==0) id_s[r] = 1.0f/(s + EPSV);
    }
    __syncthreads();
    const int tx = t&31, ty = t>>5;
    ull acc2[4][2];
    #pragma unroll
    for (int ri=0;ri<4;ri++){ acc2[ri][0]=0ull; acc2[ri][1]=0ull; }
    #pragma unroll 4
    for (int m=0;m<MMF;m++){
        float4 kvv = *(const float4*)&kv_s[m*DVV + tx*4];
        ull k0v=f2_pack(kvv.x,kvv.y), k1v=f2_pack(kvv.z,kvv.w);
        #pragma unroll
        for (int ri=0;ri<4;ri++){
            ull pp = f2_dup(ph_s[(ty + ri*8)*257 + m]);
            f2_fma(acc2[ri][0], pp, k0v);
            f2_fma(acc2[ri][1], pp, k1v);
        }
    }
    #pragma unroll
    for (int ri=0;ri<4;ri++){
        const int r = ty + ri*8;
        const float idn = id_s[r];
        float p0,p1,p2,p3;
        f2_unpack(acc2[ri][0], p0, p1);
        f2_unpack(acc2[ri][1], p2, p3);
        float4 o; o.x=p0*idn; o.y=p1*idn; o.z=p2*idn; o.w=p3*idn;
        *(float4*)(outp + (size_t)(b*SS + row0 + r)*DVV + tx*4) = o;
    }
}

// ---------------------------------------------------------------------------
extern "C" void kernel_launch(void* const* d_in, const int* in_sizes, int n_in,
                              void* d_out, int out_size)
{
    (void)in_sizes; (void)n_in; (void)out_size;
    const float* x     = (const float*)d_in[0];
    const float* Wq    = (const float*)d_in[1];
    const float* bq    = (const float*)d_in[2];
    const float* Wk    = (const float*)d_in[3];
    const float* bk    = (const float*)d_in[4];
    const float* Wv    = (const float*)d_in[5];
    const float* bv    = (const float*)d_in[6];
    const float* omega = (const float*)d_in[7];
    float* outp = (float*)d_out;

    const int k2_smem = K2_SMEM_FLOATS * (int)sizeof(float);
    const int k4_smem = K4_SMEM_FLOATS * (int)sizeof(float);
    cudaFuncSetAttribute(k_feat, cudaFuncAttributeMaxDynamicSharedMemorySize, k2_smem);
    cudaFuncSetAttribute(k_out,  cudaFuncAttributeMaxDynamicSharedMemorySize, k4_smem);

    k_init<<<1, 32>>>();
    k_qkv<<<dim3(NROWS/128, 3), 256>>>(x, Wq, bq, Wk, bk, Wv, bv);
    k_feat<<<dim3(NROWS/32, 2), 256, k2_smem>>>(omega);
    k_kv<<<dim3(BB*NCHUNK, 2), 256>>>();
    k_kvred<<<(BB*MMF*DVV + BB*MMF + 255)/256, 256>>>();
    k_out<<<dim3(SS/32, BB), 256, k4_smem>>>(outp);
}

// round 11
// speedup vs baseline: 1.9063x; 1.5731x over previous
#include <cuda_runtime.h>
#include <cuda_bf16.h>
#include <math.h>

// Problem constants
#define BB 8
#define SS 4096
#define DM 1024
#define DKK 128
#define DVV 128
#define MMF 256
#define NROWS (BB*SS)           // 32768
#define QK_SCALE 0.29730177875068026f   // 128^-0.25
#define EPSV 1e-6f
#define NCHUNK 16
#define SCH (SS/NCHUNK)         // 256

typedef unsigned long long ull;

// ---------------- f32x2 SIMD helpers (FFMA2) ----------------
__device__ __forceinline__ ull f2_dup(float a){
    ull r; asm("mov.b64 %0, {%1, %1};" : "=l"(r) : "f"(a)); return r;
}
__device__ __forceinline__ ull f2_pack(float lo, float hi){
    ull r; asm("mov.b64 %0, {%1, %2};" : "=l"(r) : "f"(lo), "f"(hi)); return r;
}
__device__ __forceinline__ void f2_unpack(ull v, float& lo, float& hi){
    asm("mov.b64 {%0, %1}, %2;" : "=f"(lo), "=f"(hi) : "l"(v));
}
__device__ __forceinline__ void f2_fma(ull& d, ull a, ull b){
    asm("fma.rn.f32x2 %0, %1, %2, %3;" : "=l"(d) : "l"(a), "l"(b), "l"(d));
}

// ---------------- warp-MMA helpers (baseline PTX, sm_80+: safe on compute_103)
__device__ __forceinline__ unsigned smem_u32(const void* p){
    unsigned a; asm("{ .reg .u64 t; cvta.to.shared.u64 t, %1; cvt.u32.u64 %0, t; }" : "=r"(a) : "l"(p));
    return a;
}
__device__ __forceinline__ void ldmx4(unsigned& r0, unsigned& r1, unsigned& r2, unsigned& r3, unsigned addr){
    asm volatile("ldmatrix.sync.aligned.m8n8.x4.shared.b16 {%0,%1,%2,%3}, [%4];"
        : "=r"(r0), "=r"(r1), "=r"(r2), "=r"(r3) : "r"(addr));
}
__device__ __forceinline__ void mma_bf16(float* d, const unsigned* a, const unsigned* b){
    asm volatile("mma.sync.aligned.m16n8k16.row.col.f32.bf16.bf16.f32 "
        "{%0,%1,%2,%3}, {%4,%5,%6,%7}, {%8,%9}, {%0,%1,%2,%3};"
        : "+f"(d[0]), "+f"(d[1]), "+f"(d[2]), "+f"(d[3])
        : "r"(a[0]), "r"(a[1]), "r"(a[2]), "r"(a[3]), "r"(b[0]), "r"(b[1]));
}
#define SWZ128(off) ((off) ^ (((off) >> 3) & 0x70))

// ---------------- scratch globals (no allocation allowed) ----------------
__device__ float g_q[NROWS*DKK];
__device__ float g_k[NROWS*DKK];
__device__ float g_v[NROWS*DVV];
__device__ float g_phiq[NROWS*MMF];
__device__ float g_pk[NROWS*MMF];
__device__ float g_kv_part[BB*NCHUNK*MMF*DVV];
__device__ float g_ks_part[BB*NCHUNK*MMF];
__device__ float g_kv[BB*MMF*DVV];
__device__ float g_ksum[BB*MMF];
__device__ unsigned int g_gmax_bits;
// W transposed K-major bf16 hi/lo: [o][n=128][k=1024]
__device__ __nv_bfloat16 g_wth[3*128*1024];
__device__ __nv_bfloat16 g_wtl[3*128*1024];
// x split bf16 hi/lo, row-major [row=32768][k=1024]
__device__ __nv_bfloat16 g_xh[(size_t)NROWS*DM];
__device__ __nv_bfloat16 g_xl[(size_t)NROWS*DM];

__device__ __forceinline__ unsigned int fenc(float f){
    unsigned int u = __float_as_uint(f);
    return (u & 0x80000000u) ? ~u : (u | 0x80000000u);
}
__device__ __forceinline__ float fdec(unsigned int u){
    return __uint_as_float((u & 0x80000000u) ? (u ^ 0x80000000u) : ~u);
}

__global__ void k_init(){
    if (threadIdx.x == 0) g_gmax_bits = fenc(-INFINITY);
}

// ---------------------------------------------------------------------------
// K0a: preconvert W -> transposed K-major bf16 hi/lo. 384 blocks x 256 thr.
// ---------------------------------------------------------------------------
__global__ void k_wcvt(const float* __restrict__ Wq, const float* __restrict__ Wk,
                       const float* __restrict__ Wv)
{
    const int idx = blockIdx.x*256 + threadIdx.x;       // 98304 total
    const int o = idx >> 15;
    const int rem = idx & 32767;
    const int n = rem >> 8;
    const int k4 = (rem & 255) * 4;
    const float* W = (o==0)?Wq:((o==1)?Wk:Wv);
    __nv_bfloat16 h[4], l[4];
    #pragma unroll
    for (int j=0;j<4;j++){
        float w = W[(size_t)(k4+j)*DKK + n];
        h[j] = __float2bfloat16(w);
        l[j] = __float2bfloat16(w - __bfloat162float(h[j]));
    }
    const size_t dst = (size_t)(o*128 + n)*1024 + k4;
    *(__nv_bfloat162*)(g_wth + dst)     = __nv_bfloat162(h[0], h[1]);
    *(__nv_bfloat162*)(g_wth + dst + 2) = __nv_bfloat162(h[2], h[3]);
    *(__nv_bfloat162*)(g_wtl + dst)     = __nv_bfloat162(l[0], l[1]);
    *(__nv_bfloat162*)(g_wtl + dst + 2) = __nv_bfloat162(l[2], l[3]);
}

// ---------------------------------------------------------------------------
// K0b: preconvert x -> bf16 hi/lo. 32768 blocks x 256 thr, 1 float4 each.
// ---------------------------------------------------------------------------
__global__ void k_xcvt(const float* __restrict__ x)
{
    const size_t e = (size_t)blockIdx.x*256 + threadIdx.x;   // 8388608
    const size_t r = e >> 8;
    const int c4 = (int)(e & 255) * 4;
    float4 v = *(const float4*)(x + r*DM + c4);
    __nv_bfloat16 h0=__float2bfloat16(v.x), h1=__float2bfloat16(v.y);
    __nv_bfloat16 h2=__float2bfloat16(v.z), h3=__float2bfloat16(v.w);
    __nv_bfloat16 l0=__float2bfloat16(v.x-__bfloat162float(h0));
    __nv_bfloat16 l1=__float2bfloat16(v.y-__bfloat162float(h1));
    __nv_bfloat16 l2=__float2bfloat16(v.z-__bfloat162float(h2));
    __nv_bfloat16 l3=__float2bfloat16(v.w-__bfloat162float(h3));
    const size_t dst = r*DM + c4;
    *(__nv_bfloat162*)(g_xh + dst)     = __nv_bfloat162(h0, h1);
    *(__nv_bfloat162*)(g_xh + dst + 2) = __nv_bfloat162(h2, h3);
    *(__nv_bfloat162*)(g_xl + dst)     = __nv_bfloat162(l0, l1);
    *(__nv_bfloat162*)(g_xl + dst + 2) = __nv_bfloat162(l2, l3);
}

// ---------------------------------------------------------------------------
// K1: warp-MMA QKV GEMM. grid = (256, 3); 256 threads = 8 warps (2m x 4n).
// Block tile 128x128, warp tile 64x32, K chunks of 64 staged in smem (SWZ128).
// Split-bf16: D += Ah*Bh + Ah*Bl + Al*Bh (fp32 accum).
// ---------------------------------------------------------------------------
#define SA_H 0
#define SA_L 16384
#define SB_H 32768
#define SB_L 49152
#define QM_SMEM 65536

__global__ __launch_bounds__(256,2) void k_qkv_mma(
    const float* __restrict__ bq, const float* __restrict__ bk,
    const float* __restrict__ bv)
{
    extern __shared__ char sm[];
    const unsigned sb = smem_u32(sm);
    const int t = threadIdx.x;
    const int wid = t >> 5, ln = t & 31;
    const int warp_m = wid & 1, warp_n = wid >> 1;
    const int o = blockIdx.y;
    const int row0 = blockIdx.x * 128;
    const float* bia = (o==0)?bq:((o==1)?bk:bv);
    float* outp      = (o==0)?g_q:((o==1)?g_k:g_v);
    const float scl  = (o==2)?1.0f:QK_SCALE;

    // per-lane ldmatrix address components
    const int row_in = ln & 7, seg = ln >> 3;
    const int aml = row_in + 8*(seg & 1);       // A: m offset within 16
    const int akl = 8*(seg >> 1);               // A: k offset within 16
    const int bnl = row_in + 8*(seg >> 1);      // B: n offset within 16
    const int bkl = 8*(seg & 1);                // B: k offset within 16

    float acc[4][4][4];
    #pragma unroll
    for (int mt=0;mt<4;mt++)
        #pragma unroll
        for (int nt=0;nt<4;nt++)
            #pragma unroll
            for (int i=0;i<4;i++) acc[mt][nt][i]=0.f;

    for (int ch = 0; ch < 16; ch++){
        const int k0 = ch*64;
        __syncthreads();
        // ---- stage 4 tiles: Ah/Al (x rows) + Bh/Bl (W cols), 128x64 bf16 ----
        #pragma unroll
        for (int i = 0; i < 4; i++){
            const int e = t + i*256;            // 1024 16B-units per tile
            const int r = e >> 3, u = e & 7;
            const unsigned dsw = SWZ128((unsigned)((r<<7) + (u<<4)));
            const size_t xoff = (size_t)(row0 + r)*DM + k0 + u*8;
            const size_t woff = (size_t)(o*128 + r)*1024 + k0 + u*8;
            *(uint4*)(sm + SA_H + dsw) = *(const uint4*)(g_xh + xoff);
            *(uint4*)(sm + SA_L + dsw) = *(const uint4*)(g_xl + xoff);
            *(uint4*)(sm + SB_H + dsw) = *(const uint4*)(g_wth + woff);
            *(uint4*)(sm + SB_L + dsw) = *(const uint4*)(g_wtl + woff);
        }
        __syncthreads();
        // ---- 4 ksteps of 16 ----
        #pragma unroll
        for (int ks = 0; ks < 4; ks++){
            unsigned bh[4][2], bl[4][2];
            #pragma unroll
            for (int np = 0; np < 2; np++){
                const unsigned boff = SWZ128(
                    (unsigned)(((warp_n*32 + np*16 + bnl)<<7) + ((ks*16 + bkl)<<1)));
                unsigned r0,r1,r2,r3;
                ldmx4(r0,r1,r2,r3, sb + SB_H + boff);
                bh[np*2][0]=r0; bh[np*2][1]=r1; bh[np*2+1][0]=r2; bh[np*2+1][1]=r3;
                ldmx4(r0,r1,r2,r3, sb + SB_L + boff);
                bl[np*2][0]=r0; bl[np*2][1]=r1; bl[np*2+1][0]=r2; bl[np*2+1][1]=r3;
            }
            #pragma unroll
            for (int mt = 0; mt < 4; mt++){
                const unsigned aoff = SWZ128(
                    (unsigned)(((warp_m*64 + mt*16 + aml)<<7) + ((ks*16 + akl)<<1)));
                unsigned ah[4], al[4];
                ldmx4(ah[0],ah[1],ah[2],ah[3], sb + SA_H + aoff);
                ldmx4(al[0],al[1],al[2],al[3], sb + SA_L + aoff);
                #pragma unroll
                for (int nt = 0; nt < 4; nt++){
                    mma_bf16(acc[mt][nt], ah, bh[nt]);
                    mma_bf16(acc[mt][nt], ah, bl[nt]);
                    mma_bf16(acc[mt][nt], al, bh[nt]);
                }
            }
        }
    }

    // ---- epilogue: (acc + bias) * scale, fragment-layout stores ----
    #pragma unroll
    for (int mt = 0; mt < 4; mt++){
        const int row = row0 + warp_m*64 + mt*16 + (ln>>2);
        #pragma unroll
        for (int nt = 0; nt < 4; nt++){
            const int col = warp_n*32 + nt*8 + (ln&3)*2;
            const float b0 = bia[col], b1 = bia[col+1];
            float2 v0, v1;
            v0.x = (acc[mt][nt][0] + b0)*scl; v0.y = (acc[mt][nt][1] + b1)*scl;
            v1.x = (acc[mt][nt][2] + b0)*scl; v1.y = (acc[mt][nt][3] + b1)*scl;
            *(float2*)(outp + (size_t)row*DKK + col)     = v0;
            *(float2*)(outp + (size_t)(row+8)*DKK + col) = v1;
        }
    }
}

// ---------------------------------------------------------------------------
// K2: feature projections (FFMA2). grid = (NROWS/32, 2).
// ---------------------------------------------------------------------------
#define K2_OST 132
#define K2_RST 132
#define K2_PST 257
#define K2_SMEM_FLOATS (256*K2_OST + 32*K2_RST + 32*K2_PST + 32 + 32 + 8)

__global__ __launch_bounds__(256,1) void k_feat(const float* __restrict__ omega)
{
    extern __shared__ float sm2[];
    float* om_s = sm2;
    float* rw_s = om_s + 256*K2_OST;
    float* pq_s = rw_s + 32*K2_RST;
    float* sq_s = pq_s + 32*K2_PST;
    float* rx_s = sq_s + 32;
    float* rd_s = rx_s + 32;
    const int t = threadIdx.x;
    const int isK = blockIdx.y;
    const float* src = isK ? g_k : g_q;
    const int row0 = blockIdx.x*32;

    #pragma unroll
    for (int i=0;i<32;i++){
        int idx = t + i*256;
        int m = idx>>5, j = (idx&31)*4;
        float4 v = *(const float4*)(omega + (size_t)m*DKK + j);
        *(float4*)&om_s[m*K2_OST + j] = v;
    }
    #pragma unroll
    for (int i=0;i<4;i++){
        int idx = t + i*256;
        int r = idx>>5, j = (idx&31)*4;
        float4 v = *(const float4*)(src + (size_t)(row0+r)*DKK + j);
        *(float4*)&rw_s[r*K2_RST + j] = v;
    }
    __syncthreads();
    {   // 0.5*||row||^2
        int r = t>>3, c = t&7;
        float s=0.f;
        #pragma unroll
        for (int j=0;j<16;j++){ float v = rw_s[r*K2_RST + c*16 + j]; s += v*v; }
        s += __shfl_down_sync(0xffffffffu, s, 4, 8);
        s += __shfl_down_sync(0xffffffffu, s, 2, 8);
        s += __shfl_down_sync(0xffffffffu, s, 1, 8);
        if (c==0) sq_s[r] = 0.5f*s;
    }
    __syncthreads();

    const int mb = t&63;
    const int r0 = (t>>6)*8;
    ull acc2[4][8];
    #pragma unroll
    for (int mi=0;mi<4;mi++)
        #pragma unroll
        for (int ri=0;ri<8;ri++) acc2[mi][ri]=0ull;

    for (int j4=0;j4<DKK;j4+=4){
        ull rp0[8], rp1[8];
        #pragma unroll
        for (int ri=0;ri<8;ri++){
            float4 v = *(const float4*)&rw_s[(r0+ri)*K2_RST + j4];
            rp0[ri]=f2_pack(v.x,v.y); rp1[ri]=f2_pack(v.z,v.w);
        }
        #pragma unroll
        for (int mi=0;mi<4;mi++){
            float4 w = *(const float4*)&om_s[(mb + mi*64)*K2_OST + j4];
            ull o0=f2_pack(w.x,w.y), o1=f2_pack(w.z,w.w);
            #pragma unroll
            for (int ri=0;ri<8;ri++){
                f2_fma(acc2[mi][ri], o0, rp0[ri]);
                f2_fma(acc2[mi][ri], o1, rp1[ri]);
            }
        }
    }
    #pragma unroll
    for (int mi=0;mi<4;mi++)
        #pragma unroll
        for (int ri=0;ri<8;ri++){
            float lo,hi; f2_unpack(acc2[mi][ri], lo, hi);
            pq_s[(r0+ri)*K2_PST + mb + mi*64] = (lo+hi) - sq_s[r0+ri];
        }
    __syncthreads();

    if (!isK){
        int r = t>>3, c = t&7;
        float mx = -INFINITY;
        #pragma unroll
        for (int i=0;i<32;i++) mx = fmaxf(mx, pq_s[r*K2_PST + c + 8*i]);
        mx = fmaxf(mx, __shfl_down_sync(0xffffffffu, mx, 4, 8));
        mx = fmaxf(mx, __shfl_down_sync(0xffffffffu, mx, 2, 8));
        mx = fmaxf(mx, __shfl_down_sync(0xffffffffu, mx, 1, 8));
        if (c==0) rx_s[r] = mx;
        __syncthreads();
        float* dst = g_phiq + (size_t)row0*MMF;
        for (int r2=0;r2<32;r2++)
            dst[r2*MMF + t] = __expf(pq_s[r2*K2_PST + t] - rx_s[r2]) * 0.0625f;
    } else {
        float mx = -INFINITY;
        float* dst = g_pk + (size_t)row0*MMF;
        for (int r2=0;r2<32;r2++){
            float v = pq_s[r2*K2_PST + t];
            dst[r2*MMF + t] = v;
            mx = fmaxf(mx, v);
        }
        #pragma unroll
        for (int o=16;o>0;o>>=1) mx = fmaxf(mx, __shfl_down_sync(0xffffffffu, mx, o));
        if ((t&31)==0) rd_s[t>>5] = mx;
        __syncthreads();
        if (t==0){
            float m2 = rd_s[0];
            #pragma unroll
            for (int i=1;i<8;i++) m2 = fmaxf(m2, rd_s[i]);
            atomicMax(&g_gmax_bits, fenc(m2));
        }
    }
}

// ---------------------------------------------------------------------------
// K3: kv partials (FFMA2). grid = (B*NCHUNK, 2).
// ---------------------------------------------------------------------------
__global__ __launch_bounds__(256,2) void k_kv()
{
    __shared__ float As[8][132];
    __shared__ float Bs[8][132];
    __shared__ float ks_s[128];
    const int t = threadIdx.x;
    const int b = blockIdx.x >> 4;
    const int chunk = blockIdx.x & 15;
    const int mtile = blockIdx.y;
    const float gmax = fdec(g_gmax_bits);
    const int ty = t>>4, tx = t&15;
    const int sr = t>>5, c4 = (t&31)*4;
    const size_t srow_base = (size_t)(b*SS + chunk*SCH + sr);

    ull acc2[8][4];
    #pragma unroll
    for (int i=0;i<8;i++)
        #pragma unroll
        for (int j=0;j<4;j++) acc2[i][j]=0ull;
    float ksl[4] = {0.f,0.f,0.f,0.f};

    for (int s0=0;s0<SCH;s0+=8){
        const size_t srow = srow_base + s0;
        float4 pv = *(const float4*)(g_pk + srow*MMF + mtile*128 + c4);
        float4 vv = *(const float4*)(g_v  + srow*DVV + c4);
        float4 ev;
        ev.x = __expf(pv.x - gmax)*0.0625f;
        ev.y = __expf(pv.y - gmax)*0.0625f;
        ev.z = __expf(pv.z - gmax)*0.0625f;
        ev.w = __expf(pv.w - gmax)*0.0625f;
        ksl[0]+=ev.x; ksl[1]+=ev.y; ksl[2]+=ev.z; ksl[3]+=ev.w;
        __syncthreads();
        *(float4*)&As[sr][c4] = ev;
        *(float4*)&Bs[sr][c4] = vv;
        __syncthreads();
        #pragma unroll
        for (int kk=0;kk<8;kk++){
            float4 a0 = *(const float4*)&As[kk][ty*4];
            float4 a1 = *(const float4*)&As[kk][64+ty*4];
            float4 b0 = *(const float4*)&Bs[kk][tx*4];
            float4 b1 = *(const float4*)&Bs[kk][64+tx*4];
            ull bb0 = f2_pack(b0.x,b0.y), bb1 = f2_pack(b0.z,b0.w);
            ull bb2 = f2_pack(b1.x,b1.y), bb3 = f2_pack(b1.z,b1.w);
            ull aa[8];
            aa[0]=f2_dup(a0.x); aa[1]=f2_dup(a0.y); aa[2]=f2_dup(a0.z); aa[3]=f2_dup(a0.w);
            aa[4]=f2_dup(a1.x); aa[5]=f2_dup(a1.y); aa[6]=f2_dup(a1.z); aa[7]=f2_dup(a1.w);
            #pragma unroll
            for (int i=0;i<8;i++){
                f2_fma(acc2[i][0], aa[i], bb0);
                f2_fma(acc2[i][1], aa[i], bb1);
                f2_fma(acc2[i][2], aa[i], bb2);
                f2_fma(acc2[i][3], aa[i], bb3);
            }
        }
    }
    float* kvp = g_kv_part + (size_t)(b*NCHUNK + chunk)*MMF*DVV + (size_t)mtile*128*DVV;
    #pragma unroll
    for (int i=0;i<8;i++){
        const int m = (i<4)? (ty*4+i) : (64+ty*4+(i-4));
        float p0,p1,p2,p3;
        {
            f2_unpack(acc2[i][0], p0, p1);
            f2_unpack(acc2[i][1], p2, p3);
            float4 o; o.x=p0; o.y=p1; o.z=p2; o.w=p3;
            *(float4*)(kvp + (size_t)m*DVV + tx*4) = o;
        }
        {
            f2_unpack(acc2[i][2], p0, p1);
            f2_unpack(acc2[i][3], p2, p3);
            float4 o; o.x=p0; o.y=p1; o.z=p2; o.w=p3;
            *(float4*)(kvp + (size_t)m*DVV + 64 + tx*4) = o;
        }
    }
    if (t<128) ks_s[t]=0.f;
    __syncthreads();
    atomicAdd(&ks_s[c4+0], ksl[0]);
    atomicAdd(&ks_s[c4+1], ksl[1]);
    atomicAdd(&ks_s[c4+2], ksl[2]);
    atomicAdd(&ks_s[c4+3], ksl[3]);
    __syncthreads();
    if (t<128)
        g_ks_part[(size_t)(b*NCHUNK+chunk)*MMF + mtile*128 + t] = ks_s[t];
}

// K3b: reduce chunk partials (deterministic)
__global__ void k_kvred(){
    const int idx = blockIdx.x*256 + threadIdx.x;
    const int KVTOT = BB*MMF*DVV;
    if (idx < KVTOT){
        const int b = idx >> 15;
        const int rem = idx & 32767;
        float s=0.f;
        #pragma unroll
        for (int c=0;c<NCHUNK;c++) s += g_kv_part[(size_t)(b*NCHUNK+c)*MMF*DVV + rem];
        g_kv[idx]=s;
    } else {
        const int j = idx - KVTOT;
        if (j < BB*MMF){
            const int b = j >> 8; const int m = j & 255;
            float s=0.f;
            #pragma unroll
            for (int c=0;c<NCHUNK;c++) s += g_ks_part[(size_t)(b*NCHUNK+c)*MMF + m];
            g_ksum[j]=s;
        }
    }
}

// ---------------------------------------------------------------------------
// K4: output GEMM + normalize (FFMA2). grid = (S/32, B).
// ---------------------------------------------------------------------------
#define K4_SMEM_FLOATS (MMF*DVV + 256 + 32*257 + 32)

__global__ __launch_bounds__(256,1) void k_out(float* __restrict__ outp)
{
    extern __shared__ float sm4[];
    float* kv_s = sm4;
    float* ks_s = kv_s + MMF*DVV;
    float* ph_s = ks_s + 256;
    float* id_s = ph_s + 32*257;
    const int t = threadIdx.x;
    const int b = blockIdx.y;
    const int row0 = blockIdx.x*32;

    #pragma unroll
    for (int i=0;i<32;i++){
        const int idx = (t + i*256)*4;
        *(float4*)&kv_s[idx] = *(const float4*)(g_kv + (size_t)b*MMF*DVV + idx);
    }
    ks_s[t] = g_ksum[b*MMF + t];
    #pragma unroll
    for (int i=0;i<8;i++){
        const int idx = t + i*256;
        const int r = idx>>6, c = (idx&63)*4;
        float4 v = *(const float4*)(g_phiq + (size_t)(b*SS + row0 + r)*MMF + c);
        float* d = &ph_s[r*257 + c];
        d[0]=v.x; d[1]=v.y; d[2]=v.z; d[3]=v.w;
    }
    __syncthreads();
    {
        int r = t>>3, c = t&7;
        float s=0.f;
        #pragma unroll
        for (int i=0;i<32;i++){ const int m = c + 8*i; s += ph_s[r*257 + m]*ks_s[m]; }
        s += __shfl_down_sync(0xffffffffu, s, 4, 8);
        s += __shfl_down_sync(0xffffffffu, s, 2, 8);
        s += __shfl_down_sync(0xffffffffu, s, 1, 8);
        if (c==0) id_s[r] = 1.0f/(s + EPSV);
    }
    __syncthreads();
    const int tx = t&31, ty = t>>5;
    ull acc2[4][2];
    #pragma unroll
    for (int ri=0;ri<4;ri++){ acc2[ri][0]=0ull; acc2[ri][1]=0ull; }
    #pragma unroll 4
    for (int m=0;m<MMF;m++){
        float4 kvv = *(const float4*)&kv_s[m*DVV + tx*4];
        ull k0v=f2_pack(kvv.x,kvv.y), k1v=f2_pack(kvv.z,kvv.w);
        #pragma unroll
        for (int ri=0;ri<4;ri++){
            ull pp = f2_dup(ph_s[(ty + ri*8)*257 + m]);
            f2_fma(acc2[ri][0], pp, k0v);
            f2_fma(acc2[ri][1], pp, k1v);
        }
    }
    #pragma unroll
    for (int ri=0;ri<4;ri++){
        const int r = ty + ri*8;
        const float idn = id_s[r];
        float p0,p1,p2,p3;
        f2_unpack(acc2[ri][0], p0, p1);
        f2_unpack(acc2[ri][1], p2, p3);
        float4 o; o.x=p0*idn; o.y=p1*idn; o.z=p2*idn; o.w=p3*idn;
        *(float4*)(outp + (size_t)(b*SS + row0 + r)*DVV + tx*4) = o;
    }
}

// ---------------------------------------------------------------------------
extern "C" void kernel_launch(void* const* d_in, const int* in_sizes, int n_in,
                              void* d_out, int out_size)
{
    (void)in_sizes; (void)n_in; (void)out_size;
    const float* x     = (const float*)d_in[0];
    const float* Wq    = (const float*)d_in[1];
    const float* bq    = (const float*)d_in[2];
    const float* Wk    = (const float*)d_in[3];
    const float* bk    = (const float*)d_in[4];
    const float* Wv    = (const float*)d_in[5];
    const float* bv    = (const float*)d_in[6];
    const float* omega = (const float*)d_in[7];
    float* outp = (float*)d_out;

    const int k2_smem = K2_SMEM_FLOATS * (int)sizeof(float);
    const int k4_smem = K4_SMEM_FLOATS * (int)sizeof(float);
    cudaFuncSetAttribute(k_qkv_mma, cudaFuncAttributeMaxDynamicSharedMemorySize, QM_SMEM);
    cudaFuncSetAttribute(k_feat, cudaFuncAttributeMaxDynamicSharedMemorySize, k2_smem);
    cudaFuncSetAttribute(k_out,  cudaFuncAttributeMaxDynamicSharedMemorySize, k4_smem);

    k_init<<<1, 32>>>();
    k_wcvt<<<384, 256>>>(Wq, Wk, Wv);
    k_xcvt<<<NROWS*DM/(256*4), 256>>>(x);
    k_qkv_mma<<<dim3(NROWS/128, 3), 256, QM_SMEM>>>(bq, bk, bv);
    k_feat<<<dim3(NROWS/32, 2), 256, k2_smem>>>(omega);
    k_kv<<<dim3(BB*NCHUNK, 2), 256>>>();
    k_kvred<<<(BB*MMF*DVV + BB*MMF + 255)/256, 256>>>();
    k_out<<<dim3(SS/32, BB), 256, k4_smem>>>(outp);
}

// round 14
// speedup vs baseline: 1.9360x; 1.0156x over previous
#include <cuda_runtime.h>
#include <cuda_bf16.h>
#include <math.h>

// Problem constants
#define BB 8
#define SS 4096
#define DM 1024
#define DKK 128
#define DVV 128
#define MMF 256
#define NROWS (BB*SS)           // 32768
#define QK_SCALE 0.29730177875068026f   // 128^-0.25
#define EPSV 1e-6f
#define NCHUNK 16
#define SCH (SS/NCHUNK)         // 256

typedef unsigned long long ull;

// ---------------- f32x2 SIMD helpers (FFMA2) ----------------
__device__ __forceinline__ ull f2_dup(float a){
    ull r; asm("mov.b64 %0, {%1, %1};" : "=l"(r) : "f"(a)); return r;
}
__device__ __forceinline__ ull f2_pack(float lo, float hi){
    ull r; asm("mov.b64 %0, {%1, %2};" : "=l"(r) : "f"(lo), "f"(hi)); return r;
}
__device__ __forceinline__ void f2_unpack(ull v, float& lo, float& hi){
    asm("mov.b64 {%0, %1}, %2;" : "=f"(lo), "=f"(hi) : "l"(v));
}
__device__ __forceinline__ void f2_fma(ull& d, ull a, ull b){
    asm("fma.rn.f32x2 %0, %1, %2, %3;" : "=l"(d) : "l"(a), "l"(b), "l"(d));
}

// ---------------- warp-MMA helpers (baseline PTX, sm_80+: safe on compute_103)
__device__ __forceinline__ unsigned smem_u32(const void* p){
    unsigned a; asm("{ .reg .u64 t; cvta.to.shared.u64 t, %1; cvt.u32.u64 %0, t; }" : "=r"(a) : "l"(p));
    return a;
}
__device__ __forceinline__ void ldmx4(unsigned& r0, unsigned& r1, unsigned& r2, unsigned& r3, unsigned addr){
    asm volatile("ldmatrix.sync.aligned.m8n8.x4.shared.b16 {%0,%1,%2,%3}, [%4];"
        : "=r"(r0), "=r"(r1), "=r"(r2), "=r"(r3) : "r"(addr));
}
__device__ __forceinline__ void mma_bf16(float* d, const unsigned* a, const unsigned* b){
    asm volatile("mma.sync.aligned.m16n8k16.row.col.f32.bf16.bf16.f32 "
        "{%0,%1,%2,%3}, {%4,%5,%6,%7}, {%8,%9}, {%0,%1,%2,%3};"
        : "+f"(d[0]), "+f"(d[1]), "+f"(d[2]), "+f"(d[3])
        : "r"(a[0]), "r"(a[1]), "r"(a[2]), "r"(a[3]), "r"(b[0]), "r"(b[1]));
}
#define SWZ128(off) ((off) ^ (((off) >> 3) & 0x70))

// ---------------- scratch globals (no allocation allowed) ----------------
__device__ float g_q[NROWS*DKK];
__device__ float g_k[NROWS*DKK];
__device__ float g_v[NROWS*DVV];
__device__ float g_phiq[NROWS*MMF];      // raw q logits (exp'd in k_out)
__device__ float g_pk[NROWS*MMF];        // raw k logits (exp'd in k_kv)
__device__ float g_kv_part[BB*NCHUNK*MMF*DVV];
__device__ float g_ks_part[BB*NCHUNK*MMF];
__device__ float g_kv[BB*MMF*DVV];
__device__ float g_ksum[BB*MMF];
__device__ unsigned int g_gmax_bits;
// W transposed K-major bf16 hi/lo: [o][n=128][k=1024]
__device__ __nv_bfloat16 g_wth[3*128*1024];
__device__ __nv_bfloat16 g_wtl[3*128*1024];
// x split bf16 hi/lo, row-major [row=32768][k=1024]
__device__ __nv_bfloat16 g_xh[(size_t)NROWS*DM];
__device__ __nv_bfloat16 g_xl[(size_t)NROWS*DM];
// omega split bf16 hi/lo, [m=256][k=128] (K-major already)
__device__ __nv_bfloat16 g_omh[MMF*DKK];
__device__ __nv_bfloat16 g_oml[MMF*DKK];

__device__ __forceinline__ unsigned int fenc(float f){
    unsigned int u = __float_as_uint(f);
    return (u & 0x80000000u) ? ~u : (u | 0x80000000u);
}
__device__ __forceinline__ float fdec(unsigned int u){
    return __uint_as_float((u & 0x80000000u) ? (u ^ 0x80000000u) : ~u);
}

__global__ void k_init(){
    if (threadIdx.x == 0) g_gmax_bits = fenc(-INFINITY);
}

// ---------------------------------------------------------------------------
// K0a: preconvert W -> transposed K-major bf16 hi/lo. 384 blocks x 256 thr.
// ---------------------------------------------------------------------------
__global__ void k_wcvt(const float* __restrict__ Wq, const float* __restrict__ Wk,
                       const float* __restrict__ Wv)
{
    const int idx = blockIdx.x*256 + threadIdx.x;       // 98304 total
    const int o = idx >> 15;
    const int rem = idx & 32767;
    const int n = rem >> 8;
    const int k4 = (rem & 255) * 4;
    const float* W = (o==0)?Wq:((o==1)?Wk:Wv);
    __nv_bfloat16 h[4], l[4];
    #pragma unroll
    for (int j=0;j<4;j++){
        float w = W[(size_t)(k4+j)*DKK + n];
        h[j] = __float2bfloat16(w);
        l[j] = __float2bfloat16(w - __bfloat162float(h[j]));
    }
    const size_t dst = (size_t)(o*128 + n)*1024 + k4;
    *(__nv_bfloat162*)(g_wth + dst)     = __nv_bfloat162(h[0], h[1]);
    *(__nv_bfloat162*)(g_wth + dst + 2) = __nv_bfloat162(h[2], h[3]);
    *(__nv_bfloat162*)(g_wtl + dst)     = __nv_bfloat162(l[0], l[1]);
    *(__nv_bfloat162*)(g_wtl + dst + 2) = __nv_bfloat162(l[2], l[3]);
}

// ---------------------------------------------------------------------------
// K0b: preconvert x -> bf16 hi/lo. 1 float4 per thread.
// ---------------------------------------------------------------------------
__global__ void k_xcvt(const float* __restrict__ x)
{
    const size_t e = (size_t)blockIdx.x*256 + threadIdx.x;   // 8388608
    const size_t r = e >> 8;
    const int c4 = (int)(e & 255) * 4;
    float4 v = *(const float4*)(x + r*DM + c4);
    __nv_bfloat16 h0=__float2bfloat16(v.x), h1=__float2bfloat16(v.y);
    __nv_bfloat16 h2=__float2bfloat16(v.z), h3=__float2bfloat16(v.w);
    __nv_bfloat16 l0=__float2bfloat16(v.x-__bfloat162float(h0));
    __nv_bfloat16 l1=__float2bfloat16(v.y-__bfloat162float(h1));
    __nv_bfloat16 l2=__float2bfloat16(v.z-__bfloat162float(h2));
    __nv_bfloat16 l3=__float2bfloat16(v.w-__bfloat162float(h3));
    const size_t dst = r*DM + c4;
    *(__nv_bfloat162*)(g_xh + dst)     = __nv_bfloat162(h0, h1);
    *(__nv_bfloat162*)(g_xh + dst + 2) = __nv_bfloat162(h2, h3);
    *(__nv_bfloat162*)(g_xl + dst)     = __nv_bfloat162(l0, l1);
    *(__nv_bfloat162*)(g_xl + dst + 2) = __nv_bfloat162(l2, l3);
}

// ---------------------------------------------------------------------------
// K0c: preconvert omega -> bf16 hi/lo (layout already K-major). grid 32.
// ---------------------------------------------------------------------------
__global__ void k_ocvt(const float* __restrict__ omega)
{
    const int e4 = (blockIdx.x*256 + threadIdx.x) * 4;   // 32768 elems
    float4 v = *(const float4*)(omega + e4);
    __nv_bfloat16 h0=__float2bfloat16(v.x), h1=__float2bfloat16(v.y);
    __nv_bfloat16 h2=__float2bfloat16(v.z), h3=__float2bfloat16(v.w);
    __nv_bfloat16 l0=__float2bfloat16(v.x-__bfloat162float(h0));
    __nv_bfloat16 l1=__float2bfloat16(v.y-__bfloat162float(h1));
    __nv_bfloat16 l2=__float2bfloat16(v.z-__bfloat162float(h2));
    __nv_bfloat16 l3=__float2bfloat16(v.w-__bfloat162float(h3));
    *(__nv_bfloat162*)(g_omh + e4)     = __nv_bfloat162(h0, h1);
    *(__nv_bfloat162*)(g_omh + e4 + 2) = __nv_bfloat162(h2, h3);
    *(__nv_bfloat162*)(g_oml + e4)     = __nv_bfloat162(l0, l1);
    *(__nv_bfloat162*)(g_oml + e4 + 2) = __nv_bfloat162(l2, l3);
}

// ---------------------------------------------------------------------------
// K1: warp-MMA QKV GEMM (unchanged from measured R11 version).
// ---------------------------------------------------------------------------
#define SA_H 0
#define SA_L 16384
#define SB_H 32768
#define SB_L 49152
#define QM_SMEM 65536

__global__ __launch_bounds__(256,2) void k_qkv_mma(
    const float* __restrict__ bq, const float* __restrict__ bk,
    const float* __restrict__ bv)
{
    extern __shared__ char sm[];
    const unsigned sb = smem_u32(sm);
    const int t = threadIdx.x;
    const int wid = t >> 5, ln = t & 31;
    const int warp_m = wid & 1, warp_n = wid >> 1;
    const int o = blockIdx.y;
    const int row0 = blockIdx.x * 128;
    const float* bia = (o==0)?bq:((o==1)?bk:bv);
    float* outp      = (o==0)?g_q:((o==1)?g_k:g_v);
    const float scl  = (o==2)?1.0f:QK_SCALE;

    const int row_in = ln & 7, seg = ln >> 3;
    const int aml = row_in + 8*(seg & 1);
    const int akl = 8*(seg >> 1);
    const int bnl = row_in + 8*(seg >> 1);
    const int bkl = 8*(seg & 1);

    float acc[4][4][4];
    #pragma unroll
    for (int mt=0;mt<4;mt++)
        #pragma unroll
        for (int nt=0;nt<4;nt++)
            #pragma unroll
            for (int i=0;i<4;i++) acc[mt][nt][i]=0.f;

    for (int ch = 0; ch < 16; ch++){
        const int k0 = ch*64;
        __syncthreads();
        #pragma unroll
        for (int i = 0; i < 4; i++){
            const int e = t + i*256;
            const int r = e >> 3, u = e & 7;
            const unsigned dsw = SWZ128((unsigned)((r<<7) + (u<<4)));
            const size_t xoff = (size_t)(row0 + r)*DM + k0 + u*8;
            const size_t woff = (size_t)(o*128 + r)*1024 + k0 + u*8;
            *(uint4*)(sm + SA_H + dsw) = *(const uint4*)(g_xh + xoff);
            *(uint4*)(sm + SA_L + dsw) = *(const uint4*)(g_xl + xoff);
            *(uint4*)(sm + SB_H + dsw) = *(const uint4*)(g_wth + woff);
            *(uint4*)(sm + SB_L + dsw) = *(const uint4*)(g_wtl + woff);
        }
        __syncthreads();
        #pragma unroll
        for (int ks = 0; ks < 4; ks++){
            unsigned bh[4][2], bl[4][2];
            #pragma unroll
            for (int np = 0; np < 2; np++){
                const unsigned boff = SWZ128(
                    (unsigned)(((warp_n*32 + np*16 + bnl)<<7) + ((ks*16 + bkl)<<1)));
                unsigned r0,r1,r2,r3;
                ldmx4(r0,r1,r2,r3, sb + SB_H + boff);
                bh[np*2][0]=r0; bh[np*2][1]=r1; bh[np*2+1][0]=r2; bh[np*2+1][1]=r3;
                ldmx4(r0,r1,r2,r3, sb + SB_L + boff);
                bl[np*2][0]=r0; bl[np*2][1]=r1; bl[np*2+1][0]=r2; bl[np*2+1][1]=r3;
            }
            #pragma unroll
            for (int mt = 0; mt < 4; mt++){
                const unsigned aoff = SWZ128(
                    (unsigned)(((warp_m*64 + mt*16 + aml)<<7) + ((ks*16 + akl)<<1)));
                unsigned ah[4], al[4];
                ldmx4(ah[0],ah[1],ah[2],ah[3], sb + SA_H + aoff);
                ldmx4(al[0],al[1],al[2],al[3], sb + SA_L + aoff);
                #pragma unroll
                for (int nt = 0; nt < 4; nt++){
                    mma_bf16(acc[mt][nt], ah, bh[nt]);
                    mma_bf16(acc[mt][nt], ah, bl[nt]);
                    mma_bf16(acc[mt][nt], al, bh[nt]);
                }
            }
        }
    }

    #pragma unroll
    for (int mt = 0; mt < 4; mt++){
        const int row = row0 + warp_m*64 + mt*16 + (ln>>2);
        #pragma unroll
        for (int nt = 0; nt < 4; nt++){
            const int col = warp_n*32 + nt*8 + (ln&3)*2;
            const float b0 = bia[col], b1 = bia[col+1];
            float2 v0, v1;
            v0.x = (acc[mt][nt][0] + b0)*scl; v0.y = (acc[mt][nt][1] + b1)*scl;
            v1.x = (acc[mt][nt][2] + b0)*scl; v1.y = (acc[mt][nt][3] + b1)*scl;
            *(float2*)(outp + (size_t)row*DKK + col)     = v0;
            *(float2*)(outp + (size_t)(row+8)*DKK + col) = v1;
        }
    }
}

// ---------------------------------------------------------------------------
// K2: warp-MMA feature projection. grid = (256, 2 feat-halves, 2 q/k).
// A = q/k rows (fp32 -> split bf16 in-kernel, + fused 0.5||y||^2 via smem
// atomics); B = omega split bf16 (K-major). Writes RAW logits:
//   q -> g_phiq (exp'd later in k_out), k -> g_pk (exp'd in k_kv)
// k path also atomicMax's the global max.
// ---------------------------------------------------------------------------
#define FM_SMEM (65536 + 1024)

__global__ __launch_bounds__(256,2) void k_feat_mma()
{
    extern __shared__ char sm[];
    const unsigned sb = smem_u32(sm);
    float* sq_s  = (float*)(sm + 65536);     // 128 floats
    float* red_s = sq_s + 128;               // 8 floats
    const int t = threadIdx.x;
    const int wid = t >> 5, ln = t & 31;
    const int warp_m = wid & 1, warp_n = wid >> 1;
    const int fh  = blockIdx.y;
    const int isK = blockIdx.z;
    const int row0 = blockIdx.x * 128;
    const float* src = isK ? g_k : g_q;
    float* dst       = isK ? g_pk : g_phiq;

    const int row_in = ln & 7, seg = ln >> 3;
    const int aml = row_in + 8*(seg & 1);
    const int akl = 8*(seg >> 1);
    const int bnl = row_in + 8*(seg >> 1);
    const int bkl = 8*(seg & 1);

    float acc[4][4][4];
    #pragma unroll
    for (int mt=0;mt<4;mt++)
        #pragma unroll
        for (int nt=0;nt<4;nt++)
            #pragma unroll
            for (int i=0;i<4;i++) acc[mt][nt][i]=0.f;
    if (t < 128) sq_s[t] = 0.f;

    for (int ch = 0; ch < 2; ch++){
        const int k0 = ch*64;
        __syncthreads();
        // ---- A: fp32 rows -> split bf16 tiles + sumsq ----
        #pragma unroll
        for (int i = 0; i < 8; i++){
            const int e = t + i*256;            // 2048 float4-groups
            const int r = e >> 4, c = (e & 15) * 4;
            float4 v = *(const float4*)(src + (size_t)(row0 + r)*DKK + k0 + c);
            atomicAdd(&sq_s[r], v.x*v.x + v.y*v.y + v.z*v.z + v.w*v.w);
            __nv_bfloat16 h0=__float2bfloat16(v.x), h1=__float2bfloat16(v.y);
            __nv_bfloat16 h2=__float2bfloat16(v.z), h3=__float2bfloat16(v.w);
            __nv_bfloat16 l0=__float2bfloat16(v.x-__bfloat162float(h0));
            __nv_bfloat16 l1=__float2bfloat16(v.y-__bfloat162float(h1));
            __nv_bfloat16 l2=__float2bfloat16(v.z-__bfloat162float(h2));
            __nv_bfloat16 l3=__float2bfloat16(v.w-__bfloat162float(h3));
            const unsigned off = SWZ128((unsigned)(r*128 + c*2));
            __nv_bfloat162 hp[2] = { __nv_bfloat162(h0,h1), __nv_bfloat162(h2,h3) };
            __nv_bfloat162 lp[2] = { __nv_bfloat162(l0,l1), __nv_bfloat162(l2,l3) };
            *(ull*)(sm + SA_H + off) = *(ull*)hp;
            *(ull*)(sm + SA_L + off) = *(ull*)lp;
        }
        // ---- B: omega tiles (already bf16 K-major) ----
        #pragma unroll
        for (int i = 0; i < 4; i++){
            const int e = t + i*256;
            const int n = e >> 3, u = e & 7;
            const unsigned dsw = SWZ128((unsigned)((n<<7) + (u<<4)));
            const size_t woff = (size_t)(fh*128 + n)*DKK + k0 + u*8;
            *(uint4*)(sm + SB_H + dsw) = *(const uint4*)(g_omh + woff);
            *(uint4*)(sm + SB_L + dsw) = *(const uint4*)(g_oml + woff);
        }
        __syncthreads();
        #pragma unroll
        for (int ks = 0; ks < 4; ks++){
            unsigned bh[4][2], bl[4][2];
            #pragma unroll
            for (int np = 0; np < 2; np++){
                const unsigned boff = SWZ128(
                    (unsigned)(((warp_n*32 + np*16 + bnl)<<7) + ((ks*16 + bkl)<<1)));
                unsigned r0,r1,r2,r3;
                ldmx4(r0,r1,r2,r3, sb + SB_H + boff);
                bh[np*2][0]=r0; bh[np*2][1]=r1; bh[np*2+1][0]=r2; bh[np*2+1][1]=r3;
                ldmx4(r0,r1,r2,r3, sb + SB_L + boff);
                bl[np*2][0]=r0; bl[np*2][1]=r1; bl[np*2+1][0]=r2; bl[np*2+1][1]=r3;
            }
            #pragma unroll
            for (int mt = 0; mt < 4; mt++){
                const unsigned aoff = SWZ128(
                    (unsigned)(((warp_m*64 + mt*16 + aml)<<7) + ((ks*16 + akl)<<1)));
                unsigned ah[4], al[4];
                ldmx4(ah[0],ah[1],ah[2],ah[3], sb + SA_H + aoff);
                ldmx4(al[0],al[1],al[2],al[3], sb + SA_L + aoff);
                #pragma unroll
                for (int nt = 0; nt < 4; nt++){
                    mma_bf16(acc[mt][nt], ah, bh[nt]);
                    mma_bf16(acc[mt][nt], ah, bl[nt]);
                    mma_bf16(acc[mt][nt], al, bh[nt]);
                }
            }
        }
    }

    // ---- epilogue: logit = proj - 0.5*||y||^2 ; store raw; k-path max ----
    float mymax = -INFINITY;
    #pragma unroll
    for (int mt = 0; mt < 4; mt++){
        const int rl = warp_m*64 + mt*16 + (ln>>2);
        const float s0 = 0.5f*sq_s[rl], s1 = 0.5f*sq_s[rl+8];
        #pragma unroll
        for (int nt = 0; nt < 4; nt++){
            const int col = fh*128 + warp_n*32 + nt*8 + (ln&3)*2;
            float2 v0, v1;
            v0.x = acc[mt][nt][0] - s0; v0.y = acc[mt][nt][1] - s0;
            v1.x = acc[mt][nt][2] - s1; v1.y = acc[mt][nt][3] - s1;
            *(float2*)(dst + (size_t)(row0+rl)*MMF + col)   = v0;
            *(float2*)(dst + (size_t)(row0+rl+8)*MMF + col) = v1;
            if (isK){
                mymax = fmaxf(mymax, fmaxf(fmaxf(v0.x, v0.y), fmaxf(v1.x, v1.y)));
            }
        }
    }
    if (isK){
        #pragma unroll
        for (int o2=16;o2>0;o2>>=1) mymax = fmaxf(mymax, __shfl_down_sync(0xffffffffu, mymax, o2));
        if (ln == 0) red_s[wid] = mymax;
        __syncthreads();
        if (t == 0){
            float m2 = red_s[0];
            #pragma unroll
            for (int i=1;i<8;i++) m2 = fmaxf(m2, red_s[i]);
            atomicMax(&g_gmax_bits, fenc(m2));
        }
    }
}

// ---------------------------------------------------------------------------
// K3: kv partials (FFMA2, exp(pk - gmax) fused). grid = (B*NCHUNK, 2).
// ---------------------------------------------------------------------------
__global__ __launch_bounds__(256,2) void k_kv()
{
    __shared__ float As[8][132];
    __shared__ float Bs[8][132];
    __shared__ float ks_s[128];
    const int t = threadIdx.x;
    const int b = blockIdx.x >> 4;
    const int chunk = blockIdx.x & 15;
    const int mtile = blockIdx.y;
    const float gmax = fdec(g_gmax_bits);
    const int ty = t>>4, tx = t&15;
    const int sr = t>>5, c4 = (t&31)*4;
    const size_t srow_base = (size_t)(b*SS + chunk*SCH + sr);

    ull acc2[8][4];
    #pragma unroll
    for (int i=0;i<8;i++)
        #pragma unroll
        for (int j=0;j<4;j++) acc2[i][j]=0ull;
    float ksl[4] = {0.f,0.f,0.f,0.f};

    for (int s0=0;s0<SCH;s0+=8){
        const size_t srow = srow_base + s0;
        float4 pv = *(const float4*)(g_pk + srow*MMF + mtile*128 + c4);
        float4 vv = *(const float4*)(g_v  + srow*DVV + c4);
        float4 ev;
        ev.x = __expf(pv.x - gmax)*0.0625f;
        ev.y = __expf(pv.y - gmax)*0.0625f;
        ev.z = __expf(pv.z - gmax)*0.0625f;
        ev.w = __expf(pv.w - gmax)*0.0625f;
        ksl[0]+=ev.x; ksl[1]+=ev.y; ksl[2]+=ev.z; ksl[3]+=ev.w;
        __syncthreads();
        *(float4*)&As[sr][c4] = ev;
        *(float4*)&Bs[sr][c4] = vv;
        __syncthreads();
        #pragma unroll
        for (int kk=0;kk<8;kk++){
            float4 a0 = *(const float4*)&As[kk][ty*4];
            float4 a1 = *(const float4*)&As[kk][64+ty*4];
            float4 b0 = *(const float4*)&Bs[kk][tx*4];
            float4 b1 = *(const float4*)&Bs[kk][64+tx*4];
            ull bb0 = f2_pack(b0.x,b0.y), bb1 = f2_pack(b0.z,b0.w);
            ull bb2 = f2_pack(b1.x,b1.y), bb3 = f2_pack(b1.z,b1.w);
            ull aa[8];
            aa[0]=f2_dup(a0.x); aa[1]=f2_dup(a0.y); aa[2]=f2_dup(a0.z); aa[3]=f2_dup(a0.w);
            aa[4]=f2_dup(a1.x); aa[5]=f2_dup(a1.y); aa[6]=f2_dup(a1.z); aa[7]=f2_dup(a1.w);
            #pragma unroll
            for (int i=0;i<8;i++){
                f2_fma(acc2[i][0], aa[i], bb0);
                f2_fma(acc2[i][1], aa[i], bb1);
                f2_fma(acc2[i][2], aa[i], bb2);
                f2_fma(acc2[i][3], aa[i], bb3);
            }
        }
    }
    float* kvp = g_kv_part + (size_t)(b*NCHUNK + chunk)*MMF*DVV + (size_t)mtile*128*DVV;
    #pragma unroll
    for (int i=0;i<8;i++){
        const int m = (i<4)? (ty*4+i) : (64+ty*4+(i-4));
        float p0,p1,p2,p3;
        {
            f2_unpack(acc2[i][0], p0, p1);
            f2_unpack(acc2[i][1], p2, p3);
            float4 o; o.x=p0; o.y=p1; o.z=p2; o.w=p3;
            *(float4*)(kvp + (size_t)m*DVV + tx*4) = o;
        }
        {
            f2_unpack(acc2[i][2], p0, p1);
            f2_unpack(acc2[i][3], p2, p3);
            float4 o; o.x=p0; o.y=p1; o.z=p2; o.w=p3;
            *(float4*)(kvp + (size_t)m*DVV + 64 + tx*4) = o;
        }
    }
    if (t<128) ks_s[t]=0.f;
    __syncthreads();
    atomicAdd(&ks_s[c4+0], ksl[0]);
    atomicAdd(&ks_s[c4+1], ksl[1]);
    atomicAdd(&ks_s[c4+2], ksl[2]);
    atomicAdd(&ks_s[c4+3], ksl[3]);
    __syncthreads();
    if (t<128)
        g_ks_part[(size_t)(b*NCHUNK+chunk)*MMF + mtile*128 + t] = ks_s[t];
}

// K3b: reduce chunk partials (deterministic)
__global__ void k_kvred(){
    const int idx = blockIdx.x*256 + threadIdx.x;
    const int KVTOT = BB*MMF*DVV;
    if (idx < KVTOT){
        const int b = idx >> 15;
        const int rem = idx & 32767;
        float s=0.f;
        #pragma unroll
        for (int c=0;c<NCHUNK;c++) s += g_kv_part[(size_t)(b*NCHUNK+c)*MMF*DVV + rem];
        g_kv[idx]=s;
    } else {
        const int j = idx - KVTOT;
        if (j < BB*MMF){
            const int b = j >> 8; const int m = j & 255;
            float s=0.f;
            #pragma unroll
            for (int c=0;c<NCHUNK;c++) s += g_ks_part[(size_t)(b*NCHUNK+c)*MMF + m];
            g_ksum[j]=s;
        }
    }
}

// ---------------------------------------------------------------------------
// K4: output GEMM + normalize (FFMA2). Now ALSO does q-path rowmax + exp
// on the staged raw logits (MUFU rides otherwise-idle pipe here).
// ---------------------------------------------------------------------------
#define K4_SMEM_FLOATS (MMF*DVV + 256 + 32*257 + 32 + 32)

__global__ __launch_bounds__(256,1) void k_out(float* __restrict__ outp)
{
    extern __shared__ float sm4[];
    float* kv_s = sm4;
    float* ks_s = kv_s + MMF*DVV;
    float* ph_s = ks_s + 256;
    float* id_s = ph_s + 32*257;
    float* rx_s = id_s + 32;
    const int t = threadIdx.x;
    const int b = blockIdx.y;
    const int row0 = blockIdx.x*32;

    #pragma unroll
    for (int i=0;i<32;i++){
        const int idx = (t + i*256)*4;
        *(float4*)&kv_s[idx] = *(const float4*)(g_kv + (size_t)b*MMF*DVV + idx);
    }
    ks_s[t] = g_ksum[b*MMF + t];
    #pragma unroll
    for (int i=0;i<8;i++){
        const int idx = t + i*256;
        const int r = idx>>6, c = (idx&63)*4;
        float4 v = *(const float4*)(g_phiq + (size_t)(b*SS + row0 + r)*MMF + c);
        float* d = &ph_s[r*257 + c];
        d[0]=v.x; d[1]=v.y; d[2]=v.z; d[3]=v.w;
    }
    __syncthreads();
    {   // per-row max of raw logits
        int r = t>>3, c = t&7;
        float mx = -INFINITY;
        #pragma unroll
        for (int i=0;i<32;i++) mx = fmaxf(mx, ph_s[r*257 + c + 8*i]);
        mx = fmaxf(mx, __shfl_down_sync(0xffffffffu, mx, 4, 8));
        mx = fmaxf(mx, __shfl_down_sync(0xffffffffu, mx, 2, 8));
        mx = fmaxf(mx, __shfl_down_sync(0xffffffffu, mx, 1, 8));
        if (c==0) rx_s[r] = mx;
    }
    __syncthreads();
    // exp in place: phi = exp(raw - rowmax) * M^-0.5
    #pragma unroll
    for (int r2=0;r2<32;r2++)
        ph_s[r2*257 + t] = __expf(ph_s[r2*257 + t] - rx_s[r2]) * 0.0625f;
    __syncthreads();
    {
        int r = t>>3, c = t&7;
        float s=0.f;
        #pragma unroll
        for (int i=0;i<32;i++){ const int m = c + 8*i; s += ph_s[r*257 + m]*ks_s[m]; }
        s += __shfl_down_sync(0xffffffffu, s, 4, 8);
        s += __shfl_down_sync(0xffffffffu, s, 2, 8);
        s += __shfl_down_sync(0xffffffffu, s, 1, 8);
        if (c==0) id_s[r] = 1.0f/(s + EPSV);
    }
    __syncthreads();
    const int tx = t&31, ty = t>>5;
    ull acc2[4][2];
    #pragma unroll
    for (int ri=0;ri<4;ri++){ acc2[ri][0]=0ull; acc2[ri][1]=0ull; }
    #pragma unroll 4
    for (int m=0;m<MMF;m++){
        float4 kvv = *(const float4*)&kv_s[m*DVV + tx*4];
        ull k0v=f2_pack(kvv.x,kvv.y), k1v=f2_pack(kvv.z,kvv.w);
        #pragma unroll
        for (int ri=0;ri<4;ri++){
            ull pp = f2_dup(ph_s[(ty + ri*8)*257 + m]);
            f2_fma(acc2[ri][0], pp, k0v);
            f2_fma(acc2[ri][1], pp, k1v);
        }
    }
    #pragma unroll
    for (int ri=0;ri<4;ri++){
        const int r = ty + ri*8;
        const float idn = id_s[r];
        float p0,p1,p2,p3;
        f2_unpack(acc2[ri][0], p0, p1);
        f2_unpack(acc2[ri][1], p2, p3);
        float4 o; o.x=p0*idn; o.y=p1*idn; o.z=p2*idn; o.w=p3*idn;
        *(float4*)(outp + (size_t)(b*SS + row0 + r)*DVV + tx*4) = o;
    }
}

// ---------------------------------------------------------------------------
extern "C" void kernel_launch(void* const* d_in, const int* in_sizes, int n_in,
                              void* d_out, int out_size)
{
    (void)in_sizes; (void)n_in; (void)out_size;
    const float* x     = (const float*)d_in[0];
    const float* Wq    = (const float*)d_in[1];
    const float* bq    = (const float*)d_in[2];
    const float* Wk    = (const float*)d_in[3];
    const float* bk    = (const float*)d_in[4];
    const float* Wv    = (const float*)d_in[5];
    const float* bv    = (const float*)d_in[6];
    const float* omega = (const float*)d_in[7];
    float* outp = (float*)d_out;

    const int k4_smem = K4_SMEM_FLOATS * (int)sizeof(float);
    cudaFuncSetAttribute(k_qkv_mma, cudaFuncAttributeMaxDynamicSharedMemorySize, QM_SMEM);
    cudaFuncSetAttribute(k_feat_mma, cudaFuncAttributeMaxDynamicSharedMemorySize, FM_SMEM);
    cudaFuncSetAttribute(k_out,  cudaFuncAttributeMaxDynamicSharedMemorySize, k4_smem);

    k_init<<<1, 32>>>();
    k_wcvt<<<384, 256>>>(Wq, Wk, Wv);
    k_xcvt<<<NROWS*DM/(256*4), 256>>>(x);
    k_ocvt<<<32, 256>>>(omega);
    k_qkv_mma<<<dim3(NROWS/128, 3), 256, QM_SMEM>>>(bq, bk, bv);
    k_feat_mma<<<dim3(NROWS/128, 2, 2), 256, FM_SMEM>>>();
    k_kv<<<dim3(BB*NCHUNK, 2), 256>>>();
    k_kvred<<<(BB*MMF*DVV + BB*MMF + 255)/256, 256>>>();
    k_out<<<dim3(SS/32, BB), 256, k4_smem>>>(outp);
}